// round 10
// baseline (speedup 1.0000x reference)
#include <cuda_runtime.h>
#include <math.h>

// ---------------------------------------------------------------------------
// Problem dims
// ---------------------------------------------------------------------------
#define B_ 64
#define T_ 256
#define I_ 512
#define S_ 256
#define D_ 1024
#define H_ 1024
#define R_ 1280          // D_ + S_

#define GBLK 128         // persistent blocks; 1 block/SM, all co-resident
#define TPB  512         // 16 warps: 2 k-teams x 8 jl-warps
#define JPB  8
#define SPB  2

typedef unsigned long long ull;

// Scan shared memory layout (floats)
#define N_WHH  (24 * 1024)
#define N_WIH  (24 * 256)
#define N_WMVH (4 * 1024)
#define OFF_WIH   (N_WHH)
#define OFF_WMVH  (OFF_WIH + N_WIH)
#define OFF_STGA  (OFF_WMVH + N_WMVH)
#define OFF_STGB  (OFF_STGA + 8192)
#define OFF_B     (OFF_STGB + 8192)
#define SCAN_SMEM_FLOATS (OFF_B + 64)
#define SCAN_SMEM_BYTES  (SCAN_SMEM_FLOATS * 4)   // 205,056 B

// ---------------------------------------------------------------------------
// Device-global scratch. Activations (h, z) use k-PAIRED batch-last layout:
//   element (k, b) at float offset (k>>1)*128 + b*2 + (k&1)
// ---------------------------------------------------------------------------
__device__ __align__(256) float g_h[D_ * B_];
__device__ __align__(256) float g_z[S_ * B_];
__device__ __align__(256) float g_wx[2 * S_ * I_];
__device__ __align__(256) float g_bx[2 * S_];
__device__ __align__(256) float g_postx[(size_t)B_ * T_ * 2 * S_];
__device__ __align__(256) float g_rssm[(size_t)B_ * T_ * R_];
__device__ __align__(256) float g_a0[(size_t)B_ * T_ * H_];
__device__ __align__(256) float g_a1[(size_t)B_ * T_ * H_];
__device__ __align__(256) float g_dist[(size_t)B_ * T_ * I_];

__device__ unsigned g_arrive[GBLK * 32];
__device__ unsigned g_release;

// ---------------------------------------------------------------------------
// Packed-f32x2 helpers
// ---------------------------------------------------------------------------
__device__ __forceinline__ void ffma2(ull& d, ull a, ull b) {
    asm("fma.rn.f32x2 %0, %1, %2, %0;" : "+l"(d) : "l"(a), "l"(b));
}
__device__ __forceinline__ float sum2(ull v) {
    return __uint_as_float((unsigned)v) + __uint_as_float((unsigned)(v >> 32));
}
__device__ __forceinline__ ull packf2(float lo, float hi) {
    return (ull)__float_as_uint(lo) | ((ull)__float_as_uint(hi) << 32);
}
__device__ __forceinline__ unsigned tf32of(float x) {
    unsigned r; asm("cvt.rna.tf32.f32 %0, %1;" : "=r"(r) : "f"(x)); return r;
}

// ---------------------------------------------------------------------------
// Grid barrier
// ---------------------------------------------------------------------------
__device__ __forceinline__ void grid_sync(unsigned token) {
    __syncthreads();
    if (blockIdx.x == 0) {
        if (threadIdx.x > 0 && threadIdx.x < GBLK) {
            unsigned v;
            do {
                asm volatile("ld.acquire.gpu.global.u32 %0, [%1];"
                             : "=r"(v) : "l"(g_arrive + threadIdx.x * 32) : "memory");
            } while (v < token);
        }
        __syncthreads();
        if (threadIdx.x == 0) {
            asm volatile("st.release.gpu.global.u32 [%0], %1;"
                         :: "l"(&g_release), "r"(token) : "memory");
        }
    } else {
        if (threadIdx.x == 0) {
            asm volatile("st.release.gpu.global.u32 [%0], %1;"
                         :: "l"(g_arrive + blockIdx.x * 32), "r"(token) : "memory");
            unsigned v;
            do {
                asm volatile("ld.acquire.gpu.global.u32 %0, [%1];"
                             : "=r"(v) : "l"(&g_release) : "memory");
            } while (v < token);
        }
        __syncthreads();
    }
}

__device__ __forceinline__ void pfetch(float4* pf, const float4* src) {
    const int t = threadIdx.x;
#pragma unroll
    for (int i = 0; i < 4; i++) pf[i] = __ldcg(src + t + i * TPB);
}
__device__ __forceinline__ void commitS(float4* dst, const float4* pf) {
    const int t = threadIdx.x;
#pragma unroll
    for (int i = 0; i < 4; i++) dst[t + i * TPB] = pf[i];
}

// ---------------------------------------------------------------------------
// Scan inner products (unchanged from R9)
// ---------------------------------------------------------------------------
template<bool POST>
__device__ __forceinline__ void gchunk(const float* __restrict__ stg,
        const float* __restrict__ wr, const float* __restrict__ wz,
        const float* __restrict__ wn, const float* __restrict__ wp,
        int lane, int team,
        ull& R0, ull& Z0, ull& N0, ull& R1, ull& Z1, ull& N1,
        ull& P0, ull& P1)
{
    const float* base = stg + (team * 32) * 128 + 4 * lane;
#pragma unroll
    for (int i = 0; i < 16; ++i) {
        ulonglong2 a0 = *(const ulonglong2*)(base + (2 * i) * 128);
        ulonglong2 a1 = *(const ulonglong2*)(base + (2 * i + 1) * 128);
        ulonglong2 q;
        q = *(const ulonglong2*)(wr + 4 * i);
        ffma2(R0, q.x, a0.x); ffma2(R0, q.y, a1.x);
        ffma2(R1, q.x, a0.y); ffma2(R1, q.y, a1.y);
        q = *(const ulonglong2*)(wz + 4 * i);
        ffma2(Z0, q.x, a0.x); ffma2(Z0, q.y, a1.x);
        ffma2(Z1, q.x, a0.y); ffma2(Z1, q.y, a1.y);
        q = *(const ulonglong2*)(wn + 4 * i);
        ffma2(N0, q.x, a0.x); ffma2(N0, q.y, a1.x);
        ffma2(N1, q.x, a0.y); ffma2(N1, q.y, a1.y);
        if (POST) {
            q = *(const ulonglong2*)(wp + 4 * i);
            ffma2(P0, q.x, a0.x); ffma2(P0, q.y, a1.x);
            ffma2(P1, q.x, a0.y); ffma2(P1, q.y, a1.y);
        }
    }
}

__global__ void init_state_kernel() {
    const int idx = blockIdx.x * blockDim.x + threadIdx.x;
    const int stride = gridDim.x * blockDim.x;
    for (int i = idx; i < D_ * B_; i += stride) g_h[i] = 0.f;
    for (int i = idx; i < S_ * B_; i += stride) g_z[i] = 0.f;
    for (int i = idx; i < GBLK * 32; i += stride) g_arrive[i] = 0u;
    if (idx == 0) g_release = 0u;
}

__global__ void build_wx_kernel(const float* __restrict__ Wm,
                                const float* __restrict__ Wv,
                                const float* __restrict__ bm,
                                const float* __restrict__ bv) {
    const int n = blockIdx.x;
    const int s = n >> 1, mv = n & 1;
    const float* src = (mv ? Wv : Wm) + (size_t)s * (I_ + D_);
    float* dst = g_wx + (size_t)n * I_;
    for (int k = threadIdx.x; k < I_; k += blockDim.x) dst[k] = src[k];
    if (threadIdx.x == 0) g_bx[n] = mv ? bv[s] : bm[s];
}

// ---------------------------------------------------------------------------
// Persistent scan (unchanged from R9)
// ---------------------------------------------------------------------------
__global__ void __launch_bounds__(TPB, 1) scan_kernel(
    const float* __restrict__ W_ih, const float* __restrict__ W_hh,
    const float* __restrict__ b_ih, const float* __restrict__ b_hh,
    const float* __restrict__ Wm,   const float* __restrict__ Wv,
    const float* __restrict__ noise)
{
    extern __shared__ float sm[];
    float* s_whh  = sm;
    float* s_wih  = sm + OFF_WIH;
    float* s_wmvh = sm + OFF_WMVH;
    float* s_stgA = sm + OFF_STGA;
    float* s_stgB = sm + OFF_STGB;
    float* s_bih  = sm + OFF_B;
    float* s_bhh  = sm + OFF_B + 24;

    const int tid  = threadIdx.x;
    const int lane = tid & 31;
    const int wid  = tid >> 5;
    const int team = wid >> 3;
    const int wj   = wid & 7;
    const int bid  = blockIdx.x;
    const int j0g  = bid * JPB;
    const int s0g  = bid * SPB;
    const bool has_post = (wj < 4);
    const int prow = wj & 3;

    for (int v = tid; v < 24 * 256; v += TPB) {
        int row = v >> 8, c = v & 255;
        int jl = row / 3, g = row % 3;
        ((float4*)s_whh)[v] = ((const float4*)(W_hh + (size_t)(g * D_ + j0g + jl) * D_))[c];
    }
    for (int v = tid; v < 24 * 64; v += TPB) {
        int row = v >> 6, c = v & 63;
        int jl = row / 3, g = row % 3;
        ((float4*)s_wih)[v] = ((const float4*)(W_ih + (size_t)(g * D_ + j0g + jl) * S_))[c];
    }
    for (int v = tid; v < 4 * 256; v += TPB) {
        int row = v >> 8, c = v & 255;
        int sl = row >> 1, mv = row & 1;
        const float* W = (mv ? Wv : Wm) + (size_t)(s0g + sl) * (I_ + D_) + I_;
        ((float4*)s_wmvh)[v] = ((const float4*)W)[c];
    }
    if (tid < 24) {
        int jl = tid / 3, g = tid % 3;
        s_bih[tid] = b_ih[g * D_ + j0g + jl];
        s_bhh[tid] = b_hh[g * D_ + j0g + jl];
    }
    __syncthreads();

    const float* wihR = s_wih + (wj * 3 + 0) * S_;
    const float* wihZ = s_wih + (wj * 3 + 1) * S_;
    const float* wihN = s_wih + (wj * 3 + 2) * S_;
    const float* whhR = s_whh + (wj * 3 + 0) * D_;
    const float* whhZ = s_whh + (wj * 3 + 1) * D_;
    const float* whhN = s_whh + (wj * 3 + 2) * D_;
    const float* wpR  = s_wmvh + prow * D_;

    const float4* z4 = (const float4*)g_z;
    const float4* h4 = (const float4*)g_h;

    float4 pf[4];
    ull R0 = 0, Z0 = 0, R1 = 0, Z1 = 0, ghn0 = 0, ghn1 = 0;
    float hp0 = 0.f, hp1 = 0.f;
    ull du0, du1;

    pfetch(pf, z4);

    for (int t = 0; t < T_; ++t) {
        float2 px = make_float2(0.f, 0.f);
        float nz = 0.f;
        if (tid < 128) {
            int slq = tid >> 6, bq = tid & 63;
            px = __ldcg((const float2*)(g_postx +
                    ((size_t)bq * T_ + t) * (2 * S_) + 2 * (s0g + slq)));
            nz = __ldcg(noise + ((size_t)t * B_ + bq) * S_ + s0g + slq);
        }

        ull gin0 = 0, gin1 = 0;
        {
            commitS((float4*)s_stgA, pf); __syncthreads();
            pfetch(pf, z4 + 2048);
            int off = 0 * 128 + team * 64;
            gchunk<false>(s_stgA, wihR + off, wihZ + off, wihN + off, 0,
                          lane, team, R0, Z0, gin0, R1, Z1, gin1, du0, du1);
            commitS((float4*)s_stgB, pf); __syncthreads();
            off = 1 * 128 + team * 64;
            gchunk<false>(s_stgB, wihR + off, wihZ + off, wihN + off, 0,
                          lane, team, R0, Z0, gin0, R1, Z1, gin1, du0, du1);
        }

        {
            ull* red = (ull*)s_stgA;
            if (team == 1) {
                ull* r = red + (size_t)(wj * 32 + lane) * 8;
                r[0] = R0; r[1] = Z0; r[2] = gin0; r[3] = ghn0;
                r[4] = R1; r[5] = Z1; r[6] = gin1; r[7] = ghn1;
            }
            __syncthreads();
            if (team == 0) {
                const ull* r = red + (size_t)(wj * 32 + lane) * 8;
                float br = s_bih[wj * 3 + 0] + s_bhh[wj * 3 + 0];
                float bz = s_bih[wj * 3 + 1] + s_bhh[wj * 3 + 1];
                float bin = s_bih[wj * 3 + 2];
                float bhn = s_bhh[wj * 3 + 2];
                float vr0 = sum2(R0) + sum2(r[0]) + br;
                float vz0 = sum2(Z0) + sum2(r[1]) + bz;
                float gi0 = sum2(gin0) + sum2(r[2]) + bin;
                float gh0 = sum2(ghn0) + sum2(r[3]) + bhn;
                float vr1 = sum2(R1) + sum2(r[4]) + br;
                float vz1 = sum2(Z1) + sum2(r[5]) + bz;
                float gi1 = sum2(gin1) + sum2(r[6]) + bin;
                float gh1 = sum2(ghn1) + sum2(r[7]) + bhn;

                float rr0 = 1.f / (1.f + expf(-vr0));
                float zg0 = 1.f / (1.f + expf(-vz0));
                float nn0 = tanhf(gi0 + rr0 * gh0);
                float hn0 = (1.f - zg0) * nn0 + zg0 * hp0;
                float rr1 = 1.f / (1.f + expf(-vr1));
                float zg1 = 1.f / (1.f + expf(-vz1));
                float nn1 = tanhf(gi1 + rr1 * gh1);
                float hn1 = (1.f - zg1) * nn1 + zg1 * hp1;
                hp0 = hn0; hp1 = hn1;

                int j = j0g + wj;
                size_t hoff = (size_t)(j >> 1) * 128 + (j & 1);
                __stcg(&g_h[hoff + 4 * lane], hn0);
                __stcg(&g_h[hoff + 4 * lane + 2], hn1);
                g_rssm[((size_t)(2 * lane) * T_ + t) * R_ + j] = hn0;
                g_rssm[((size_t)(2 * lane + 1) * T_ + t) * R_ + j] = hn1;
            }
            R0 = 0; Z0 = 0; R1 = 0; Z1 = 0; ghn0 = 0; ghn1 = 0;
        }

        grid_sync(2 * t + 1);
        pfetch(pf, h4);

        ull P0 = 0, P1 = 0;
        for (int c = 0; c < 8; ++c) {
            float* buf = (c & 1) ? s_stgB : s_stgA;
            commitS((float4*)buf, pf); __syncthreads();
            if (c < 7) pfetch(pf, h4 + (c + 1) * 2048);
            int off = c * 128 + team * 64;
            if (has_post)
                gchunk<true>(buf, whhR + off, whhZ + off, whhN + off, wpR + off,
                             lane, team, R0, Z0, ghn0, R1, Z1, ghn1, P0, P1);
            else
                gchunk<false>(buf, whhR + off, whhZ + off, whhN + off, 0,
                              lane, team, R0, Z0, ghn0, R1, Z1, ghn1, du0, du1);
        }

        {
            ull* red2 = (ull*)s_stgA;
            if (has_post) {
                red2[(size_t)((team * 4 + prow) * 64 + 2 * lane)] = P0;
                red2[(size_t)((team * 4 + prow) * 64 + 2 * lane + 1)] = P1;
            }
            __syncthreads();
            if (tid < 128) {
                int sl = tid >> 6, b = tid & 63;
                float m = sum2(red2[(2 * sl) * 64 + b]) +
                          sum2(red2[(4 + 2 * sl) * 64 + b]) + px.x;
                float v = sum2(red2[(2 * sl + 1) * 64 + b]) +
                          sum2(red2[(4 + 2 * sl + 1) * 64 + b]) + px.y;
                float zv = nz * expf(0.5f * v) + m;
                int sg = s0g + sl;
                __stcg(&g_z[(size_t)(sg >> 1) * 128 + b * 2 + (sg & 1)], zv);
                g_rssm[((size_t)b * T_ + t) * R_ + D_ + sg] = zv;
            }
        }

        grid_sync(2 * t + 2);
        pfetch(pf, z4);
    }
}

// ---------------------------------------------------------------------------
// f32x2 GEMM (kept ONLY for the postx precompute, which feeds the recurrence)
// ---------------------------------------------------------------------------
#define GM 128
#define GN 64
#define GK 32
#define KK2 (GK / 2)

__global__ void __launch_bounds__(256, 2) gemm_f32x2_kernel(
    const float* __restrict__ A, const float* __restrict__ W,
    const float* __restrict__ bias, float* __restrict__ C,
    int M, int N, int K, int act)
{
    __shared__ ull As2[2][KK2][GM];
    __shared__ ull Ws2[2][KK2][GN];
    const int tid = threadIdx.x;
    const int bm = blockIdx.y * GM;
    const int bn = blockIdx.x * GN;
    const int tx = tid & 15, ty = tid >> 4;
    const int m0 = ty * 8, n0 = tx * 4;
    const int part = tid & 7;
    const int lrow = tid >> 3;

    ull acc[8][4];
#pragma unroll
    for (int i = 0; i < 8; ++i)
#pragma unroll
        for (int j = 0; j < 4; ++j) acc[i][j] = 0ULL;

    float4 va[4], vw[2];
#pragma unroll
    for (int i = 0; i < 4; ++i)
        va[i] = *(const float4*)(A + (size_t)(bm + lrow + i * 32) * K + part * 4);
#pragma unroll
    for (int i = 0; i < 2; ++i)
        vw[i] = *(const float4*)(W + (size_t)(bn + lrow + i * 32) * K + part * 4);

#pragma unroll
    for (int i = 0; i < 4; ++i) {
        As2[0][part * 2 + 0][lrow + i * 32] = packf2(va[i].x, va[i].y);
        As2[0][part * 2 + 1][lrow + i * 32] = packf2(va[i].z, va[i].w);
    }
#pragma unroll
    for (int i = 0; i < 2; ++i) {
        Ws2[0][part * 2 + 0][lrow + i * 32] = packf2(vw[i].x, vw[i].y);
        Ws2[0][part * 2 + 1][lrow + i * 32] = packf2(vw[i].z, vw[i].w);
    }

    const int niter = K / GK;
    int buf = 0;
    for (int kb = 0; kb < niter; ++kb) {
        __syncthreads();
        if (kb + 1 < niter) {
            int ko = (kb + 1) * GK + part * 4;
#pragma unroll
            for (int i = 0; i < 4; ++i)
                va[i] = *(const float4*)(A + (size_t)(bm + lrow + i * 32) * K + ko);
#pragma unroll
            for (int i = 0; i < 2; ++i)
                vw[i] = *(const float4*)(W + (size_t)(bn + lrow + i * 32) * K + ko);
        }
#pragma unroll
        for (int k2 = 0; k2 < KK2; ++k2) {
            ull ra[8], rw[4];
            *(ulonglong2*)&ra[0] = *(const ulonglong2*)&As2[buf][k2][m0 + 0];
            *(ulonglong2*)&ra[2] = *(const ulonglong2*)&As2[buf][k2][m0 + 2];
            *(ulonglong2*)&ra[4] = *(const ulonglong2*)&As2[buf][k2][m0 + 4];
            *(ulonglong2*)&ra[6] = *(const ulonglong2*)&As2[buf][k2][m0 + 6];
            *(ulonglong2*)&rw[0] = *(const ulonglong2*)&Ws2[buf][k2][n0 + 0];
            *(ulonglong2*)&rw[2] = *(const ulonglong2*)&Ws2[buf][k2][n0 + 2];
#pragma unroll
            for (int i = 0; i < 8; ++i)
#pragma unroll
                for (int j = 0; j < 4; ++j) ffma2(acc[i][j], ra[i], rw[j]);
        }
        if (kb + 1 < niter) {
            int nb = buf ^ 1;
#pragma unroll
            for (int i = 0; i < 4; ++i) {
                As2[nb][part * 2 + 0][lrow + i * 32] = packf2(va[i].x, va[i].y);
                As2[nb][part * 2 + 1][lrow + i * 32] = packf2(va[i].z, va[i].w);
            }
#pragma unroll
            for (int i = 0; i < 2; ++i) {
                Ws2[nb][part * 2 + 0][lrow + i * 32] = packf2(vw[i].x, vw[i].y);
                Ws2[nb][part * 2 + 1][lrow + i * 32] = packf2(vw[i].z, vw[i].w);
            }
            buf = nb;
        }
    }

    float bb[4];
#pragma unroll
    for (int j = 0; j < 4; ++j) bb[j] = bias[bn + n0 + j];
#pragma unroll
    for (int i = 0; i < 8; ++i) {
        float r[4];
#pragma unroll
        for (int j = 0; j < 4; ++j) {
            float v = sum2(acc[i][j]) + bb[j];
            r[j] = act ? (v > 0.f ? v : expm1f(v)) : v;
        }
        *(float4*)(C + (size_t)(bm + m0 + i) * N + bn + n0) =
            make_float4(r[0], r[1], r[2], r[3]);
    }
}

// ---------------------------------------------------------------------------
// Decoder GEMM on tensor cores: tf32 mma.sync m16n8k8.
// C[M,N] = act(A[M,K] @ W[N,K]^T + bias). Block 128x64x16, 8 warps (32x32 each).
// Smem: A as [k][m] ld=136, W as [k][n] ld=72 (mod 32 == 8 -> conflict-free
// fragment LDS). cvt.rna.tf32 applied at stage time; fp32 bias+ELU epilogue.
// ---------------------------------------------------------------------------
#define TM 128
#define TN 64
#define TK 16
#define LDA 136
#define LDB 72

__device__ __forceinline__ void mma_tf32(float* c, const unsigned* a, const unsigned* b) {
    asm volatile(
        "mma.sync.aligned.m16n8k8.row.col.f32.tf32.tf32.f32 "
        "{%0,%1,%2,%3}, {%4,%5,%6,%7}, {%8,%9}, {%0,%1,%2,%3};"
        : "+f"(c[0]), "+f"(c[1]), "+f"(c[2]), "+f"(c[3])
        : "r"(a[0]), "r"(a[1]), "r"(a[2]), "r"(a[3]), "r"(b[0]), "r"(b[1]));
}

__global__ void __launch_bounds__(256, 2) gemm_tf32_kernel(
    const float* __restrict__ A, const float* __restrict__ W,
    const float* __restrict__ bias, float* __restrict__ C,
    int M, int N, int K, int act)
{
    __shared__ unsigned As[2][TK][LDA];   // 17408 B
    __shared__ unsigned Bs[2][TK][LDB];   // 9216 B

    const int tid  = threadIdx.x;
    const int lane = tid & 31;
    const int warp = tid >> 5;          // 0..7
    const int wm = warp & 3, wn = warp >> 2;
    const int g = lane >> 2, tig = lane & 3;
    const int bm = blockIdx.y * TM;
    const int bn = blockIdx.x * TN;

    // loaders: A rows ar, ar+64; W row nr; k-part q*4
    const int ar = tid >> 2, q = tid & 3;

    float acc[2][4][4];
#pragma unroll
    for (int mt = 0; mt < 2; ++mt)
#pragma unroll
        for (int nt = 0; nt < 4; ++nt)
#pragma unroll
            for (int i = 0; i < 4; ++i) acc[mt][nt][i] = 0.f;

    float4 va0, va1, vw0;
    va0 = *(const float4*)(A + (size_t)(bm + ar) * K + q * 4);
    va1 = *(const float4*)(A + (size_t)(bm + ar + 64) * K + q * 4);
    vw0 = *(const float4*)(W + (size_t)(bn + ar) * K + q * 4);

#pragma unroll
    for (int j = 0; j < 4; ++j) {
        float e0 = j == 0 ? va0.x : j == 1 ? va0.y : j == 2 ? va0.z : va0.w;
        float e1 = j == 0 ? va1.x : j == 1 ? va1.y : j == 2 ? va1.z : va1.w;
        float ew = j == 0 ? vw0.x : j == 1 ? vw0.y : j == 2 ? vw0.z : vw0.w;
        As[0][q * 4 + j][ar]      = tf32of(e0);
        As[0][q * 4 + j][ar + 64] = tf32of(e1);
        Bs[0][q * 4 + j][ar]      = tf32of(ew);
    }
    __syncthreads();

    const int niter = K / TK;
    int buf = 0;
    for (int kb = 0; kb < niter; ++kb) {
        if (kb + 1 < niter) {
            int ko = (kb + 1) * TK + q * 4;
            va0 = *(const float4*)(A + (size_t)(bm + ar) * K + ko);
            va1 = *(const float4*)(A + (size_t)(bm + ar + 64) * K + ko);
            vw0 = *(const float4*)(W + (size_t)(bn + ar) * K + ko);
        }
#pragma unroll
        for (int kk = 0; kk < 2; ++kk) {
            const int k0 = kk * 8;
            unsigned af[2][4], bf[4][2];
#pragma unroll
            for (int mt = 0; mt < 2; ++mt) {
                int mb = wm * 32 + mt * 16;
                af[mt][0] = As[buf][k0 + tig][mb + g];
                af[mt][1] = As[buf][k0 + tig][mb + g + 8];
                af[mt][2] = As[buf][k0 + tig + 4][mb + g];
                af[mt][3] = As[buf][k0 + tig + 4][mb + g + 8];
            }
#pragma unroll
            for (int nt = 0; nt < 4; ++nt) {
                int nb = wn * 32 + nt * 8;
                bf[nt][0] = Bs[buf][k0 + tig][nb + g];
                bf[nt][1] = Bs[buf][k0 + tig + 4][nb + g];
            }
#pragma unroll
            for (int mt = 0; mt < 2; ++mt)
#pragma unroll
                for (int nt = 0; nt < 4; ++nt)
                    mma_tf32(acc[mt][nt], af[mt], bf[nt]);
        }
        if (kb + 1 < niter) {
            int nb2 = buf ^ 1;
#pragma unroll
            for (int j = 0; j < 4; ++j) {
                float e0 = j == 0 ? va0.x : j == 1 ? va0.y : j == 2 ? va0.z : va0.w;
                float e1 = j == 0 ? va1.x : j == 1 ? va1.y : j == 2 ? va1.z : va1.w;
                float ew = j == 0 ? vw0.x : j == 1 ? vw0.y : j == 2 ? vw0.z : vw0.w;
                As[nb2][q * 4 + j][ar]      = tf32of(e0);
                As[nb2][q * 4 + j][ar + 64] = tf32of(e1);
                Bs[nb2][q * 4 + j][ar]      = tf32of(ew);
            }
            buf = nb2;
        }
        __syncthreads();
    }

#pragma unroll
    for (int mt = 0; mt < 2; ++mt) {
#pragma unroll
        for (int nt = 0; nt < 4; ++nt) {
            int row = bm + wm * 32 + mt * 16 + g;
            int col = bn + wn * 32 + nt * 8 + 2 * tig;
            float b0 = bias[col], b1 = bias[col + 1];
            float v00 = acc[mt][nt][0] + b0, v01 = acc[mt][nt][1] + b1;
            float v10 = acc[mt][nt][2] + b0, v11 = acc[mt][nt][3] + b1;
            if (act) {
                v00 = v00 > 0.f ? v00 : expm1f(v00);
                v01 = v01 > 0.f ? v01 : expm1f(v01);
                v10 = v10 > 0.f ? v10 : expm1f(v10);
                v11 = v11 > 0.f ? v11 : expm1f(v11);
            }
            *(float2*)(C + (size_t)row * N + col) = make_float2(v00, v01);
            *(float2*)(C + (size_t)(row + 8) * N + col) = make_float2(v10, v11);
        }
    }
}

// ---------------------------------------------------------------------------
// Epilogue
// ---------------------------------------------------------------------------
__global__ void epilogue_kernel(const float* __restrict__ x, float* __restrict__ out) {
    size_t idx = (size_t)blockIdx.x * blockDim.x + threadIdx.x;
    const size_t total = (size_t)B_ * T_ * I_;
    if (idx >= total) return;
    int i = (int)(idx & (I_ - 1));
    size_t bt = idx >> 9;
    int t = (int)(bt & (T_ - 1));
    int b = (int)(bt >> 8);

    float xh;
    if (t == 0) xh = x[idx];
    else        xh = x[idx - I_] + g_dist[idx - I_];
    out[(size_t)B_ * (T_ - 1) * I_ + idx] = xh;

    if (t < T_ - 1)
        out[((size_t)b * (T_ - 1) + t) * I_ + i] = g_dist[idx];
}

// ---------------------------------------------------------------------------
// kernel_launch
// ---------------------------------------------------------------------------
extern "C" void kernel_launch(void* const* d_in, const int* in_sizes, int n_in,
                              void* d_out, int out_size) {
    const float* x     = (const float*)d_in[0];
    const float* noise = (const float*)d_in[1];
    const float* W_ih  = (const float*)d_in[2];
    const float* W_hh  = (const float*)d_in[3];
    const float* b_ih  = (const float*)d_in[4];
    const float* b_hh  = (const float*)d_in[5];
    const float* Wm    = (const float*)d_in[6];
    const float* bm    = (const float*)d_in[7];
    const float* Wv    = (const float*)d_in[8];
    const float* bv    = (const float*)d_in[9];
    const float* dW0   = (const float*)d_in[10];
    const float* db0   = (const float*)d_in[11];
    const float* dW1   = (const float*)d_in[12];
    const float* db1   = (const float*)d_in[13];
    const float* dW2   = (const float*)d_in[14];
    const float* db2   = (const float*)d_in[15];
    const float* dW3   = (const float*)d_in[16];
    const float* db3   = (const float*)d_in[17];
    float* out = (float*)d_out;

    cudaFuncSetAttribute(scan_kernel, cudaFuncAttributeMaxDynamicSharedMemorySize,
                         SCAN_SMEM_BYTES);

    void *p_rssm, *p_a0, *p_a1, *p_dist, *p_wx, *p_bx, *p_postx;
    cudaGetSymbolAddress(&p_rssm, g_rssm);
    cudaGetSymbolAddress(&p_a0, g_a0);
    cudaGetSymbolAddress(&p_a1, g_a1);
    cudaGetSymbolAddress(&p_dist, g_dist);
    cudaGetSymbolAddress(&p_wx, g_wx);
    cudaGetSymbolAddress(&p_bx, g_bx);
    cudaGetSymbolAddress(&p_postx, g_postx);

    const int M = B_ * T_;  // 16384

    init_state_kernel<<<64, 256>>>();
    build_wx_kernel<<<2 * S_, 256>>>(Wm, Wv, bm, bv);

    // postx stays fp32 (feeds the recurrence — keep numerics unchanged)
    gemm_f32x2_kernel<<<dim3((2 * S_) / GN, M / GM), 256>>>(
        x, (const float*)p_wx, (const float*)p_bx, (float*)p_postx,
        M, 2 * S_, I_, 0);

    scan_kernel<<<GBLK, TPB, SCAN_SMEM_BYTES>>>(W_ih, W_hh, b_ih, b_hh,
                                                Wm, Wv, noise);

    // decoder on tensor cores (tf32)
    gemm_tf32_kernel<<<dim3(H_ / TN, M / TM), 256>>>(
        (const float*)p_rssm, dW0, db0, (float*)p_a0, M, H_, R_, 1);
    gemm_tf32_kernel<<<dim3(H_ / TN, M / TM), 256>>>(
        (const float*)p_a0, dW1, db1, (float*)p_a1, M, H_, H_, 1);
    gemm_tf32_kernel<<<dim3(H_ / TN, M / TM), 256>>>(
        (const float*)p_a1, dW2, db2, (float*)p_a0, M, H_, H_, 1);
    gemm_tf32_kernel<<<dim3(I_ / TN, M / TM), 256>>>(
        (const float*)p_a0, dW3, db3, (float*)p_dist, M, I_, H_, 0);

    epilogue_kernel<<<(B_ * T_ * I_ + 255) / 256, 256>>>(x, out);
}

// round 11
// speedup vs baseline: 1.4170x; 1.4170x over previous
#include <cuda_runtime.h>
#include <math.h>

// ---------------------------------------------------------------------------
// Problem dims
// ---------------------------------------------------------------------------
#define B_ 64
#define T_ 256
#define I_ 512
#define S_ 256
#define D_ 1024
#define H_ 1024
#define R_ 1280          // D_ + S_

#define GBLK 128         // persistent blocks; 1 block/SM, all co-resident
#define TPB  512         // 16 warps: 4 k-teams x 4 jl-pair warps
#define JPB  8
#define SPB  2

typedef unsigned long long ull;

// Scan shared memory layout (floats)
#define N_WHH  (24 * 1024)
#define N_WIH  (24 * 256)
#define N_WMVH (4 * 1024)
#define OFF_WIH   (N_WHH)
#define OFF_WMVH  (OFF_WIH + N_WIH)
#define OFF_STGA  (OFF_WMVH + N_WMVH)
#define OFF_STGB  (OFF_STGA + 8192)
#define OFF_B     (OFF_STGB + 8192)
#define SCAN_SMEM_FLOATS (OFF_B + 64)
#define SCAN_SMEM_BYTES  (SCAN_SMEM_FLOATS * 4)   // 205,056 B

// ---------------------------------------------------------------------------
// Device-global scratch. Activations (h, z) use k-PAIRED batch-last layout:
//   element (k, b) at float offset (k>>1)*128 + b*2 + (k&1)
// ---------------------------------------------------------------------------
__device__ __align__(256) float g_h[D_ * B_];
__device__ __align__(256) float g_z[S_ * B_];
__device__ __align__(256) float g_wx[2 * S_ * I_];
__device__ __align__(256) float g_bx[2 * S_];
__device__ __align__(256) float g_postx[(size_t)B_ * T_ * 2 * S_];
__device__ __align__(256) float g_rssm[(size_t)B_ * T_ * R_];
__device__ __align__(256) float g_a0[(size_t)B_ * T_ * H_];
__device__ __align__(256) float g_a1[(size_t)B_ * T_ * H_];
__device__ __align__(256) float g_dist[(size_t)B_ * T_ * I_];

__device__ unsigned g_arrive[GBLK * 32];
__device__ unsigned g_release;

// ---------------------------------------------------------------------------
// Packed-f32x2 helpers
// ---------------------------------------------------------------------------
__device__ __forceinline__ void ffma2(ull& d, ull a, ull b) {
    asm("fma.rn.f32x2 %0, %1, %2, %0;" : "+l"(d) : "l"(a), "l"(b));
}
__device__ __forceinline__ float sum2(ull v) {
    return __uint_as_float((unsigned)v) + __uint_as_float((unsigned)(v >> 32));
}
__device__ __forceinline__ ull packf2(float lo, float hi) {
    return (ull)__float_as_uint(lo) | ((ull)__float_as_uint(hi) << 32);
}

// ---------------------------------------------------------------------------
// Grid barrier (unchanged)
// ---------------------------------------------------------------------------
__device__ __forceinline__ void grid_sync(unsigned token) {
    __syncthreads();
    if (blockIdx.x == 0) {
        if (threadIdx.x > 0 && threadIdx.x < GBLK) {
            unsigned v;
            do {
                asm volatile("ld.acquire.gpu.global.u32 %0, [%1];"
                             : "=r"(v) : "l"(g_arrive + threadIdx.x * 32) : "memory");
            } while (v < token);
        }
        __syncthreads();
        if (threadIdx.x == 0) {
            asm volatile("st.release.gpu.global.u32 [%0], %1;"
                         :: "l"(&g_release), "r"(token) : "memory");
        }
    } else {
        if (threadIdx.x == 0) {
            asm volatile("st.release.gpu.global.u32 [%0], %1;"
                         :: "l"(g_arrive + blockIdx.x * 32), "r"(token) : "memory");
            unsigned v;
            do {
                asm volatile("ld.acquire.gpu.global.u32 %0, [%1];"
                             : "=r"(v) : "l"(&g_release) : "memory");
            } while (v < token);
        }
        __syncthreads();
    }
}

__device__ __forceinline__ void pfetch(float4* pf, const float4* src) {
    const int t = threadIdx.x;
#pragma unroll
    for (int i = 0; i < 4; i++) pf[i] = __ldcg(src + t + i * TPB);
}
__device__ __forceinline__ void commitS(float4* dst, const float4* pf) {
    const int t = threadIdx.x;
#pragma unroll
    for (int i = 0; i < 4; i++) dst[t + i * TPB] = pf[i];
}

// ---------------------------------------------------------------------------
// One warp's quarter-chunk inner product: 6 GRU rows (2 jl) + optional
// posterior row. 2 batches per lane, 32 k (the warp's team quarter).
// sb = stg + team*2048 + 4*lane; weight ptrs already offset.
// ---------------------------------------------------------------------------
template<bool POST>
__device__ __forceinline__ void gchunk2(const float* __restrict__ sb,
        const float* __restrict__ ar, const float* __restrict__ az,
        const float* __restrict__ an,
        const float* __restrict__ br, const float* __restrict__ bz,
        const float* __restrict__ bn,
        const float* __restrict__ wp,
        ull& rA0, ull& rA1, ull& zA0, ull& zA1, ull& nA0, ull& nA1,
        ull& rB0, ull& rB1, ull& zB0, ull& zB1, ull& nB0, ull& nB1,
        ull& P0, ull& P1)
{
#pragma unroll
    for (int i = 0; i < 8; ++i) {
        ulonglong2 a0 = *(const ulonglong2*)(sb + (2 * i) * 128);
        ulonglong2 a1 = *(const ulonglong2*)(sb + (2 * i + 1) * 128);
        ulonglong2 q;
        q = *(const ulonglong2*)(ar + 4 * i);
        ffma2(rA0, q.x, a0.x); ffma2(rA0, q.y, a1.x);
        ffma2(rA1, q.x, a0.y); ffma2(rA1, q.y, a1.y);
        q = *(const ulonglong2*)(az + 4 * i);
        ffma2(zA0, q.x, a0.x); ffma2(zA0, q.y, a1.x);
        ffma2(zA1, q.x, a0.y); ffma2(zA1, q.y, a1.y);
        q = *(const ulonglong2*)(an + 4 * i);
        ffma2(nA0, q.x, a0.x); ffma2(nA0, q.y, a1.x);
        ffma2(nA1, q.x, a0.y); ffma2(nA1, q.y, a1.y);
        q = *(const ulonglong2*)(br + 4 * i);
        ffma2(rB0, q.x, a0.x); ffma2(rB0, q.y, a1.x);
        ffma2(rB1, q.x, a0.y); ffma2(rB1, q.y, a1.y);
        q = *(const ulonglong2*)(bz + 4 * i);
        ffma2(zB0, q.x, a0.x); ffma2(zB0, q.y, a1.x);
        ffma2(zB1, q.x, a0.y); ffma2(zB1, q.y, a1.y);
        q = *(const ulonglong2*)(bn + 4 * i);
        ffma2(nB0, q.x, a0.x); ffma2(nB0, q.y, a1.x);
        ffma2(nB1, q.x, a0.y); ffma2(nB1, q.y, a1.y);
        if (POST) {
            q = *(const ulonglong2*)(wp + 4 * i);
            ffma2(P0, q.x, a0.x); ffma2(P0, q.y, a1.x);
            ffma2(P1, q.x, a0.y); ffma2(P1, q.y, a1.y);
        }
    }
}

__device__ __forceinline__ float gru_cell(float vr, float vz, float gi,
                                          float gh, float hp) {
    float r = 1.f / (1.f + expf(-vr));
    float z = 1.f / (1.f + expf(-vz));
    float n = tanhf(gi + r * gh);
    return (1.f - z) * n + z * hp;
}

__global__ void init_state_kernel() {
    const int idx = blockIdx.x * blockDim.x + threadIdx.x;
    const int stride = gridDim.x * blockDim.x;
    for (int i = idx; i < D_ * B_; i += stride) g_h[i] = 0.f;
    for (int i = idx; i < S_ * B_; i += stride) g_z[i] = 0.f;
    for (int i = idx; i < GBLK * 32; i += stride) g_arrive[i] = 0u;
    if (idx == 0) g_release = 0u;
}

__global__ void build_wx_kernel(const float* __restrict__ Wm,
                                const float* __restrict__ Wv,
                                const float* __restrict__ bm,
                                const float* __restrict__ bv) {
    const int n = blockIdx.x;
    const int s = n >> 1, mv = n & 1;
    const float* src = (mv ? Wv : Wm) + (size_t)s * (I_ + D_);
    float* dst = g_wx + (size_t)n * I_;
    for (int k = threadIdx.x; k < I_; k += blockDim.x) dst[k] = src[k];
    if (threadIdx.x == 0) g_bx[n] = mv ? bv[s] : bm[s];
}

// ---------------------------------------------------------------------------
// Persistent scan: 16 warps = 4 k-teams x 4 warps; each warp owns 2 jl
// (6 GRU rows) + 1 posterior row; 2 batches per lane.
// ---------------------------------------------------------------------------
__global__ void __launch_bounds__(TPB, 1) scan_kernel(
    const float* __restrict__ W_ih, const float* __restrict__ W_hh,
    const float* __restrict__ b_ih, const float* __restrict__ b_hh,
    const float* __restrict__ Wm,   const float* __restrict__ Wv,
    const float* __restrict__ noise)
{
    extern __shared__ float sm[];
    float* s_whh  = sm;
    float* s_wih  = sm + OFF_WIH;
    float* s_wmvh = sm + OFF_WMVH;
    float* s_stgA = sm + OFF_STGA;
    float* s_stgB = sm + OFF_STGB;
    float* s_bih  = sm + OFF_B;
    float* s_bhh  = sm + OFF_B + 24;

    const int tid  = threadIdx.x;
    const int lane = tid & 31;
    const int wid  = tid >> 5;
    const int team = wid >> 2;        // 0..3 (k-quarter)
    const int wj   = wid & 3;         // jl-pair 0..3; also posterior row
    const int bid  = blockIdx.x;
    const int j0g  = bid * JPB;
    const int s0g  = bid * SPB;
    const int jl0  = 2 * wj, jl1 = 2 * wj + 1;

    for (int v = tid; v < 24 * 256; v += TPB) {
        int row = v >> 8, c = v & 255;
        int jl = row / 3, g = row % 3;
        ((float4*)s_whh)[v] = ((const float4*)(W_hh + (size_t)(g * D_ + j0g + jl) * D_))[c];
    }
    for (int v = tid; v < 24 * 64; v += TPB) {
        int row = v >> 6, c = v & 63;
        int jl = row / 3, g = row % 3;
        ((float4*)s_wih)[v] = ((const float4*)(W_ih + (size_t)(g * D_ + j0g + jl) * S_))[c];
    }
    for (int v = tid; v < 4 * 256; v += TPB) {
        int row = v >> 8, c = v & 255;
        int sl = row >> 1, mv = row & 1;
        const float* W = (mv ? Wv : Wm) + (size_t)(s0g + sl) * (I_ + D_) + I_;
        ((float4*)s_wmvh)[v] = ((const float4*)W)[c];
    }
    if (tid < 24) {
        int jl = tid / 3, g = tid % 3;
        s_bih[tid] = b_ih[g * D_ + j0g + jl];
        s_bhh[tid] = b_hh[g * D_ + j0g + jl];
    }
    __syncthreads();

    // per-warp weight row base pointers
    const float* ihAr = s_wih + (jl0 * 3 + 0) * S_;
    const float* ihAz = s_wih + (jl0 * 3 + 1) * S_;
    const float* ihAn = s_wih + (jl0 * 3 + 2) * S_;
    const float* ihBr = s_wih + (jl1 * 3 + 0) * S_;
    const float* ihBz = s_wih + (jl1 * 3 + 1) * S_;
    const float* ihBn = s_wih + (jl1 * 3 + 2) * S_;
    const float* hhAr = s_whh + (jl0 * 3 + 0) * D_;
    const float* hhAz = s_whh + (jl0 * 3 + 1) * D_;
    const float* hhAn = s_whh + (jl0 * 3 + 2) * D_;
    const float* hhBr = s_whh + (jl1 * 3 + 0) * D_;
    const float* hhBz = s_whh + (jl1 * 3 + 1) * D_;
    const float* hhBn = s_whh + (jl1 * 3 + 2) * D_;
    const float* wpR  = s_wmvh + wj * D_;

    const float4* z4 = (const float4*)g_z;
    const float4* h4 = (const float4*)g_h;
    const int sboff = team * 2048 + 4 * lane;

    float4 pf[4];
    // carried: gh r/z (gi r/z added in), gh n-gate. Quarter partials.
    ull rA0 = 0, rA1 = 0, zA0 = 0, zA1 = 0, nA0 = 0, nA1 = 0;
    ull rB0 = 0, rB1 = 0, zB0 = 0, zB1 = 0, nB0 = 0, nB1 = 0;
    float hp0 = 0.f, hp1 = 0.f, hp2 = 0.f, hp3 = 0.f;  // team 0: (jl0,b0/b1),(jl1,b0/b1)
    ull du0, du1;

    pfetch(pf, z4);

    for (int t = 0; t < T_; ++t) {
        float2 px = make_float2(0.f, 0.f);
        float nz = 0.f;
        if (tid < 128) {
            int slq = tid >> 6, bq = tid & 63;
            px = __ldcg((const float2*)(g_postx +
                    ((size_t)bq * T_ + t) * (2 * S_) + 2 * (s0g + slq)));
            nz = __ldcg(noise + ((size_t)t * B_ + bq) * S_ + s0g + slq);
        }

        // ===== (A) gi over z_{t-1}: 2 chunks; r/z into carried accs =====
        ull gA0 = 0, gA1 = 0, gB0 = 0, gB1 = 0;   // gi n-gate
        {
            commitS((float4*)s_stgA, pf); __syncthreads();
            pfetch(pf, z4 + 2048);
            int off = team * 32;
            gchunk2<false>(s_stgA + sboff, ihAr + off, ihAz + off, ihAn + off,
                           ihBr + off, ihBz + off, ihBn + off, 0,
                           rA0, rA1, zA0, zA1, gA0, gA1,
                           rB0, rB1, zB0, zB1, gB0, gB1, du0, du1);
            commitS((float4*)s_stgB, pf); __syncthreads();
            off = 128 + team * 32;
            gchunk2<false>(s_stgB + sboff, ihAr + off, ihAz + off, ihAn + off,
                           ihBr + off, ihBz + off, ihBn + off, 0,
                           rA0, rA1, zA0, zA1, gA0, gA1,
                           rB0, rB1, zB0, zB1, gB0, gB1, du0, du1);
        }

        // ---- finalize h_t: 4-way cross-team reduce (floats, stride 17) ----
        {
            if (team != 0) {
                float* r = s_stgA + ((team - 1) * 4 + wj) * 544 + lane * 17;
                r[0]  = sum2(rA0); r[1]  = sum2(rA1);
                r[2]  = sum2(zA0); r[3]  = sum2(zA1);
                r[4]  = sum2(gA0); r[5]  = sum2(gA1);
                r[6]  = sum2(nA0); r[7]  = sum2(nA1);
                r[8]  = sum2(rB0); r[9]  = sum2(rB1);
                r[10] = sum2(zB0); r[11] = sum2(zB1);
                r[12] = sum2(gB0); r[13] = sum2(gB1);
                r[14] = sum2(nB0); r[15] = sum2(nB1);
            }
            __syncthreads();
            if (team == 0) {
                float s[16];
                s[0]=sum2(rA0); s[1]=sum2(rA1); s[2]=sum2(zA0); s[3]=sum2(zA1);
                s[4]=sum2(gA0); s[5]=sum2(gA1); s[6]=sum2(nA0); s[7]=sum2(nA1);
                s[8]=sum2(rB0); s[9]=sum2(rB1); s[10]=sum2(zB0); s[11]=sum2(zB1);
                s[12]=sum2(gB0); s[13]=sum2(gB1); s[14]=sum2(nB0); s[15]=sum2(nB1);
#pragma unroll
                for (int tm = 0; tm < 3; ++tm) {
                    const float* r = s_stgA + (tm * 4 + wj) * 544 + lane * 17;
#pragma unroll
                    for (int q = 0; q < 16; ++q) s[q] += r[q];
                }
                float brA = s_bih[jl0*3+0] + s_bhh[jl0*3+0];
                float bzA = s_bih[jl0*3+1] + s_bhh[jl0*3+1];
                float biA = s_bih[jl0*3+2], bhA = s_bhh[jl0*3+2];
                float brB = s_bih[jl1*3+0] + s_bhh[jl1*3+0];
                float bzB = s_bih[jl1*3+1] + s_bhh[jl1*3+1];
                float biB = s_bih[jl1*3+2], bhB = s_bhh[jl1*3+2];

                float hnA0 = gru_cell(s[0]+brA, s[2]+bzA, s[4]+biA, s[6]+bhA, hp0);
                float hnA1 = gru_cell(s[1]+brA, s[3]+bzA, s[5]+biA, s[7]+bhA, hp1);
                float hnB0 = gru_cell(s[8]+brB, s[10]+bzB, s[12]+biB, s[14]+bhB, hp2);
                float hnB1 = gru_cell(s[9]+brB, s[11]+bzB, s[13]+biB, s[15]+bhB, hp3);
                hp0 = hnA0; hp1 = hnA1; hp2 = hnB0; hp3 = hnB1;

                // paired layout: k-pair (jl0,jl1), batches 2lane, 2lane+1
                int jp = (j0g >> 1) + wj;
                float4 hv = make_float4(hnA0, hnB0, hnA1, hnB1);
                __stcg((float4*)g_h + jp * 32 + lane, hv);
                __stcg((float2*)(g_rssm + ((size_t)(2*lane) * T_ + t) * R_ + j0g + jl0),
                       make_float2(hnA0, hnB0));
                __stcg((float2*)(g_rssm + ((size_t)(2*lane+1) * T_ + t) * R_ + j0g + jl0),
                       make_float2(hnA1, hnB1));
            }
            rA0 = 0; rA1 = 0; zA0 = 0; zA1 = 0; nA0 = 0; nA1 = 0;
            rB0 = 0; rB1 = 0; zB0 = 0; zB1 = 0; nB0 = 0; nB1 = 0;
        }

        grid_sync(2 * t + 1);
        pfetch(pf, h4);

        // ===== (B) h-pass over h_t: gh_{t+1} + posterior row, 8 chunks =====
        ull P0 = 0, P1 = 0;
        for (int c = 0; c < 8; ++c) {
            float* buf = (c & 1) ? s_stgB : s_stgA;
            commitS((float4*)buf, pf); __syncthreads();
            if (c < 7) pfetch(pf, h4 + (c + 1) * 2048);
            int off = c * 128 + team * 32;
            gchunk2<true>(buf + sboff, hhAr + off, hhAz + off, hhAn + off,
                          hhBr + off, hhBz + off, hhBn + off, wpR + off,
                          rA0, rA1, zA0, zA1, nA0, nA1,
                          rB0, rB1, zB0, zB1, nB0, nB1, P0, P1);
        }

        // ---- finalize z_t: 16-piece posterior reduce ----
        {
            ull* red2 = (ull*)s_stgA;
            *(ulonglong2*)(red2 + (size_t)(team * 4 + wj) * 64 + 2 * lane) =
                make_ulonglong2(P0, P1);
            __syncthreads();
            if (tid < 128) {
                int sl = tid >> 6, b = tid & 63;
                float m = px.x, v = px.y;
#pragma unroll
                for (int tm = 0; tm < 4; ++tm) {
                    m += sum2(red2[(size_t)(tm * 4 + 2 * sl) * 64 + b]);
                    v += sum2(red2[(size_t)(tm * 4 + 2 * sl + 1) * 64 + b]);
                }
                float zv = nz * expf(0.5f * v) + m;
                int sg = s0g + sl;
                __stcg(&g_z[(size_t)(sg >> 1) * 128 + b * 2 + (sg & 1)], zv);
                g_rssm[((size_t)b * T_ + t) * R_ + D_ + sg] = zv;
            }
        }

        grid_sync(2 * t + 2);
        pfetch(pf, z4);
    }
}

// ---------------------------------------------------------------------------
// Decoder GEMM, packed-f32x2, GK=32, double-buffered smem (R9 version).
// ---------------------------------------------------------------------------
#define GM 128
#define GN 64
#define GK 32
#define KK2 (GK / 2)

__global__ void __launch_bounds__(256, 2) gemm_f32x2_kernel(
    const float* __restrict__ A, const float* __restrict__ W,
    const float* __restrict__ bias, float* __restrict__ C,
    int M, int N, int K, int act)
{
    __shared__ ull As2[2][KK2][GM];
    __shared__ ull Ws2[2][KK2][GN];
    const int tid = threadIdx.x;
    const int bm = blockIdx.y * GM;
    const int bn = blockIdx.x * GN;
    const int tx = tid & 15, ty = tid >> 4;
    const int m0 = ty * 8, n0 = tx * 4;
    const int part = tid & 7;
    const int lrow = tid >> 3;

    ull acc[8][4];
#pragma unroll
    for (int i = 0; i < 8; ++i)
#pragma unroll
        for (int j = 0; j < 4; ++j) acc[i][j] = 0ULL;

    float4 va[4], vw[2];
#pragma unroll
    for (int i = 0; i < 4; ++i)
        va[i] = *(const float4*)(A + (size_t)(bm + lrow + i * 32) * K + part * 4);
#pragma unroll
    for (int i = 0; i < 2; ++i)
        vw[i] = *(const float4*)(W + (size_t)(bn + lrow + i * 32) * K + part * 4);

#pragma unroll
    for (int i = 0; i < 4; ++i) {
        As2[0][part * 2 + 0][lrow + i * 32] = packf2(va[i].x, va[i].y);
        As2[0][part * 2 + 1][lrow + i * 32] = packf2(va[i].z, va[i].w);
    }
#pragma unroll
    for (int i = 0; i < 2; ++i) {
        Ws2[0][part * 2 + 0][lrow + i * 32] = packf2(vw[i].x, vw[i].y);
        Ws2[0][part * 2 + 1][lrow + i * 32] = packf2(vw[i].z, vw[i].w);
    }

    const int niter = K / GK;
    int buf = 0;
    for (int kb = 0; kb < niter; ++kb) {
        __syncthreads();
        if (kb + 1 < niter) {
            int ko = (kb + 1) * GK + part * 4;
#pragma unroll
            for (int i = 0; i < 4; ++i)
                va[i] = *(const float4*)(A + (size_t)(bm + lrow + i * 32) * K + ko);
#pragma unroll
            for (int i = 0; i < 2; ++i)
                vw[i] = *(const float4*)(W + (size_t)(bn + lrow + i * 32) * K + ko);
        }
#pragma unroll
        for (int k2 = 0; k2 < KK2; ++k2) {
            ull ra[8], rw[4];
            *(ulonglong2*)&ra[0] = *(const ulonglong2*)&As2[buf][k2][m0 + 0];
            *(ulonglong2*)&ra[2] = *(const ulonglong2*)&As2[buf][k2][m0 + 2];
            *(ulonglong2*)&ra[4] = *(const ulonglong2*)&As2[buf][k2][m0 + 4];
            *(ulonglong2*)&ra[6] = *(const ulonglong2*)&As2[buf][k2][m0 + 6];
            *(ulonglong2*)&rw[0] = *(const ulonglong2*)&Ws2[buf][k2][n0 + 0];
            *(ulonglong2*)&rw[2] = *(const ulonglong2*)&Ws2[buf][k2][n0 + 2];
#pragma unroll
            for (int i = 0; i < 8; ++i)
#pragma unroll
                for (int j = 0; j < 4; ++j) ffma2(acc[i][j], ra[i], rw[j]);
        }
        if (kb + 1 < niter) {
            int nb = buf ^ 1;
#pragma unroll
            for (int i = 0; i < 4; ++i) {
                As2[nb][part * 2 + 0][lrow + i * 32] = packf2(va[i].x, va[i].y);
                As2[nb][part * 2 + 1][lrow + i * 32] = packf2(va[i].z, va[i].w);
            }
#pragma unroll
            for (int i = 0; i < 2; ++i) {
                Ws2[nb][part * 2 + 0][lrow + i * 32] = packf2(vw[i].x, vw[i].y);
                Ws2[nb][part * 2 + 1][lrow + i * 32] = packf2(vw[i].z, vw[i].w);
            }
            buf = nb;
        }
    }

    float bb[4];
#pragma unroll
    for (int j = 0; j < 4; ++j) bb[j] = bias[bn + n0 + j];
#pragma unroll
    for (int i = 0; i < 8; ++i) {
        float r[4];
#pragma unroll
        for (int j = 0; j < 4; ++j) {
            float v = sum2(acc[i][j]) + bb[j];
            r[j] = act ? (v > 0.f ? v : expm1f(v)) : v;
        }
        *(float4*)(C + (size_t)(bm + m0 + i) * N + bn + n0) =
            make_float4(r[0], r[1], r[2], r[3]);
    }
}

// ---------------------------------------------------------------------------
// Epilogue
// ---------------------------------------------------------------------------
__global__ void epilogue_kernel(const float* __restrict__ x, float* __restrict__ out) {
    size_t idx = (size_t)blockIdx.x * blockDim.x + threadIdx.x;
    const size_t total = (size_t)B_ * T_ * I_;
    if (idx >= total) return;
    int i = (int)(idx & (I_ - 1));
    size_t bt = idx >> 9;
    int t = (int)(bt & (T_ - 1));
    int b = (int)(bt >> 8);

    float xh;
    if (t == 0) xh = x[idx];
    else        xh = x[idx - I_] + g_dist[idx - I_];
    out[(size_t)B_ * (T_ - 1) * I_ + idx] = xh;

    if (t < T_ - 1)
        out[((size_t)b * (T_ - 1) + t) * I_ + i] = g_dist[idx];
}

// ---------------------------------------------------------------------------
// kernel_launch
// ---------------------------------------------------------------------------
extern "C" void kernel_launch(void* const* d_in, const int* in_sizes, int n_in,
                              void* d_out, int out_size) {
    const float* x     = (const float*)d_in[0];
    const float* noise = (const float*)d_in[1];
    const float* W_ih  = (const float*)d_in[2];
    const float* W_hh  = (const float*)d_in[3];
    const float* b_ih  = (const float*)d_in[4];
    const float* b_hh  = (const float*)d_in[5];
    const float* Wm    = (const float*)d_in[6];
    const float* bm    = (const float*)d_in[7];
    const float* Wv    = (const float*)d_in[8];
    const float* bv    = (const float*)d_in[9];
    const float* dW0   = (const float*)d_in[10];
    const float* db0   = (const float*)d_in[11];
    const float* dW1   = (const float*)d_in[12];
    const float* db1   = (const float*)d_in[13];
    const float* dW2   = (const float*)d_in[14];
    const float* db2   = (const float*)d_in[15];
    const float* dW3   = (const float*)d_in[16];
    const float* db3   = (const float*)d_in[17];
    float* out = (float*)d_out;

    cudaFuncSetAttribute(scan_kernel, cudaFuncAttributeMaxDynamicSharedMemorySize,
                         SCAN_SMEM_BYTES);

    void *p_rssm, *p_a0, *p_a1, *p_dist, *p_wx, *p_bx, *p_postx;
    cudaGetSymbolAddress(&p_rssm, g_rssm);
    cudaGetSymbolAddress(&p_a0, g_a0);
    cudaGetSymbolAddress(&p_a1, g_a1);
    cudaGetSymbolAddress(&p_dist, g_dist);
    cudaGetSymbolAddress(&p_wx, g_wx);
    cudaGetSymbolAddress(&p_bx, g_bx);
    cudaGetSymbolAddress(&p_postx, g_postx);

    const int M = B_ * T_;  // 16384

    init_state_kernel<<<64, 256>>>();
    build_wx_kernel<<<2 * S_, 256>>>(Wm, Wv, bm, bv);

    gemm_f32x2_kernel<<<dim3((2 * S_) / GN, M / GM), 256>>>(
        x, (const float*)p_wx, (const float*)p_bx, (float*)p_postx,
        M, 2 * S_, I_, 0);

    scan_kernel<<<GBLK, TPB, SCAN_SMEM_BYTES>>>(W_ih, W_hh, b_ih, b_hh,
                                                Wm, Wv, noise);

    gemm_f32x2_kernel<<<dim3(H_ / GN, M / GM), 256>>>(
        (const float*)p_rssm, dW0, db0, (float*)p_a0, M, H_, R_, 1);
    gemm_f32x2_kernel<<<dim3(H_ / GN, M / GM), 256>>>(
        (const float*)p_a0, dW1, db1, (float*)p_a1, M, H_, H_, 1);
    gemm_f32x2_kernel<<<dim3(H_ / GN, M / GM), 256>>>(
        (const float*)p_a1, dW2, db2, (float*)p_a0, M, H_, H_, 1);
    gemm_f32x2_kernel<<<dim3(I_ / GN, M / GM), 256>>>(
        (const float*)p_a0, dW3, db3, (float*)p_dist, M, I_, H_, 0);

    epilogue_kernel<<<(B_ * T_ * I_ + 255) / 256, 256>>>(x, out);
}

// round 12
// speedup vs baseline: 1.4695x; 1.0370x over previous
#include <cuda_runtime.h>
#include <math.h>

// ---------------------------------------------------------------------------
// Problem dims
// ---------------------------------------------------------------------------
#define B_ 64
#define T_ 256
#define I_ 512
#define S_ 256
#define D_ 1024
#define H_ 1024
#define R_ 1280          // D_ + S_

#define GBLK 128         // persistent blocks; 1 block/SM, all co-resident
#define TPB  512         // 16 warps: 4 k-teams x 4 jl-pair warps
#define JPB  8
#define SPB  2

typedef unsigned long long ull;

// Scan shared memory layout (floats)
#define N_WHH  (24 * 1024)
#define N_WIH  (24 * 256)
#define N_WMVH (4 * 1024)
#define OFF_WIH   (N_WHH)
#define OFF_WMVH  (OFF_WIH + N_WIH)
#define OFF_STGA  (OFF_WMVH + N_WMVH)
#define OFF_STGB  (OFF_STGA + 8192)
#define OFF_B     (OFF_STGB + 8192)
#define SCAN_SMEM_FLOATS (OFF_B + 64)
#define SCAN_SMEM_BYTES  (SCAN_SMEM_FLOATS * 4)   // 205,056 B

// ---------------------------------------------------------------------------
// Device-global scratch. Activations (h, z) use k-PAIRED batch-last layout:
//   element (k, b) at float offset (k>>1)*128 + b*2 + (k&1)
// ---------------------------------------------------------------------------
__device__ __align__(256) float g_h[D_ * B_];
__device__ __align__(256) float g_z[S_ * B_];
__device__ __align__(256) float g_wx[2 * S_ * I_];
__device__ __align__(256) float g_bx[2 * S_];
__device__ __align__(256) float g_postx[(size_t)B_ * T_ * 2 * S_];
__device__ __align__(256) float g_rssm[(size_t)B_ * T_ * R_];
__device__ __align__(256) float g_a0[(size_t)B_ * T_ * H_];
__device__ __align__(256) float g_a1[(size_t)B_ * T_ * H_];
__device__ __align__(256) float g_dist[(size_t)B_ * T_ * I_];

__device__ unsigned g_arrive[GBLK * 32];
__device__ unsigned g_release;

// ---------------------------------------------------------------------------
// Packed-f32x2 helpers
// ---------------------------------------------------------------------------
__device__ __forceinline__ void ffma2(ull& d, ull a, ull b) {
    asm("fma.rn.f32x2 %0, %1, %2, %0;" : "+l"(d) : "l"(a), "l"(b));
}
__device__ __forceinline__ float sum2(ull v) {
    return __uint_as_float((unsigned)v) + __uint_as_float((unsigned)(v >> 32));
}
__device__ __forceinline__ ull packf2(float lo, float hi) {
    return (ull)__float_as_uint(lo) | ((ull)__float_as_uint(hi) << 32);
}

// ---------------------------------------------------------------------------
// cp.async staging helpers (global -> smem, no register relay)
// ---------------------------------------------------------------------------
__device__ __forceinline__ void cpa16(unsigned dst, const void* src) {
    asm volatile("cp.async.cg.shared.global [%0], [%1], 16;" :: "r"(dst), "l"(src));
}
#define CP_COMMIT() asm volatile("cp.async.commit_group;" ::: "memory")
#define CP_WAIT0()  asm volatile("cp.async.wait_group 0;" ::: "memory")

// stage one 32 KB chunk (2048 float4)
__device__ __forceinline__ void cpa_chunk(unsigned dstu, const float4* src) {
    const int t = threadIdx.x;
#pragma unroll
    for (int i = 0; i < 4; ++i)
        cpa16(dstu + (unsigned)((t + i * TPB) * 16), src + t + i * TPB);
}
// stage the full 64 KB z (4096 float4)
__device__ __forceinline__ void cpa_z(unsigned dstu, const float4* src) {
    const int t = threadIdx.x;
#pragma unroll
    for (int i = 0; i < 8; ++i)
        cpa16(dstu + (unsigned)((t + i * TPB) * 16), src + t + i * TPB);
}

// ---------------------------------------------------------------------------
// Grid barrier
// ---------------------------------------------------------------------------
__device__ __forceinline__ void grid_sync(unsigned token) {
    __syncthreads();
    if (blockIdx.x == 0) {
        if (threadIdx.x > 0 && threadIdx.x < GBLK) {
            unsigned v;
            do {
                asm volatile("ld.acquire.gpu.global.u32 %0, [%1];"
                             : "=r"(v) : "l"(g_arrive + threadIdx.x * 32) : "memory");
            } while (v < token);
        }
        __syncthreads();
        if (threadIdx.x == 0) {
            asm volatile("st.release.gpu.global.u32 [%0], %1;"
                         :: "l"(&g_release), "r"(token) : "memory");
        }
    } else {
        if (threadIdx.x == 0) {
            asm volatile("st.release.gpu.global.u32 [%0], %1;"
                         :: "l"(g_arrive + blockIdx.x * 32), "r"(token) : "memory");
            unsigned v;
            do {
                asm volatile("ld.acquire.gpu.global.u32 %0, [%1];"
                             : "=r"(v) : "l"(&g_release) : "memory");
            } while (v < token);
        }
        __syncthreads();
    }
}

// ---------------------------------------------------------------------------
// One warp's quarter-chunk inner product: 6 GRU rows (2 jl) + optional
// posterior row. 2 batches per lane, 32 k (the warp's team quarter).
// ---------------------------------------------------------------------------
template<bool POST>
__device__ __forceinline__ void gchunk2(const float* __restrict__ sb,
        const float* __restrict__ ar, const float* __restrict__ az,
        const float* __restrict__ an,
        const float* __restrict__ br, const float* __restrict__ bz,
        const float* __restrict__ bn,
        const float* __restrict__ wp,
        ull& rA0, ull& rA1, ull& zA0, ull& zA1, ull& nA0, ull& nA1,
        ull& rB0, ull& rB1, ull& zB0, ull& zB1, ull& nB0, ull& nB1,
        ull& P0, ull& P1)
{
#pragma unroll
    for (int i = 0; i < 8; ++i) {
        ulonglong2 a0 = *(const ulonglong2*)(sb + (2 * i) * 128);
        ulonglong2 a1 = *(const ulonglong2*)(sb + (2 * i + 1) * 128);
        ulonglong2 q;
        q = *(const ulonglong2*)(ar + 4 * i);
        ffma2(rA0, q.x, a0.x); ffma2(rA0, q.y, a1.x);
        ffma2(rA1, q.x, a0.y); ffma2(rA1, q.y, a1.y);
        q = *(const ulonglong2*)(az + 4 * i);
        ffma2(zA0, q.x, a0.x); ffma2(zA0, q.y, a1.x);
        ffma2(zA1, q.x, a0.y); ffma2(zA1, q.y, a1.y);
        q = *(const ulonglong2*)(an + 4 * i);
        ffma2(nA0, q.x, a0.x); ffma2(nA0, q.y, a1.x);
        ffma2(nA1, q.x, a0.y); ffma2(nA1, q.y, a1.y);
        q = *(const ulonglong2*)(br + 4 * i);
        ffma2(rB0, q.x, a0.x); ffma2(rB0, q.y, a1.x);
        ffma2(rB1, q.x, a0.y); ffma2(rB1, q.y, a1.y);
        q = *(const ulonglong2*)(bz + 4 * i);
        ffma2(zB0, q.x, a0.x); ffma2(zB0, q.y, a1.x);
        ffma2(zB1, q.x, a0.y); ffma2(zB1, q.y, a1.y);
        q = *(const ulonglong2*)(bn + 4 * i);
        ffma2(nB0, q.x, a0.x); ffma2(nB0, q.y, a1.x);
        ffma2(nB1, q.x, a0.y); ffma2(nB1, q.y, a1.y);
        if (POST) {
            q = *(const ulonglong2*)(wp + 4 * i);
            ffma2(P0, q.x, a0.x); ffma2(P0, q.y, a1.x);
            ffma2(P1, q.x, a0.y); ffma2(P1, q.y, a1.y);
        }
    }
}

__device__ __forceinline__ float gru_cell(float vr, float vz, float gi,
                                          float gh, float hp) {
    float r = 1.f / (1.f + __expf(-vr));
    float z = 1.f / (1.f + __expf(-vz));
    float n = tanhf(gi + r * gh);
    return (1.f - z) * n + z * hp;
}

__global__ void init_state_kernel() {
    const int idx = blockIdx.x * blockDim.x + threadIdx.x;
    const int stride = gridDim.x * blockDim.x;
    for (int i = idx; i < D_ * B_; i += stride) g_h[i] = 0.f;
    for (int i = idx; i < S_ * B_; i += stride) g_z[i] = 0.f;
    for (int i = idx; i < GBLK * 32; i += stride) g_arrive[i] = 0u;
    if (idx == 0) g_release = 0u;
}

__global__ void build_wx_kernel(const float* __restrict__ Wm,
                                const float* __restrict__ Wv,
                                const float* __restrict__ bm,
                                const float* __restrict__ bv) {
    const int n = blockIdx.x;
    const int s = n >> 1, mv = n & 1;
    const float* src = (mv ? Wv : Wm) + (size_t)s * (I_ + D_);
    float* dst = g_wx + (size_t)n * I_;
    for (int k = threadIdx.x; k < I_; k += blockDim.x) dst[k] = src[k];
    if (threadIdx.x == 0) g_bx[n] = mv ? bv[s] : bm[s];
}

// ---------------------------------------------------------------------------
// Persistent scan: 16 warps = 4 k-teams x 4 warps; cp.async staging.
// ---------------------------------------------------------------------------
__global__ void __launch_bounds__(TPB, 1) scan_kernel(
    const float* __restrict__ W_ih, const float* __restrict__ W_hh,
    const float* __restrict__ b_ih, const float* __restrict__ b_hh,
    const float* __restrict__ Wm,   const float* __restrict__ Wv,
    const float* __restrict__ noise)
{
    extern __shared__ float sm[];
    float* s_whh  = sm;
    float* s_wih  = sm + OFF_WIH;
    float* s_wmvh = sm + OFF_WMVH;
    float* s_stgA = sm + OFF_STGA;
    float* s_stgB = sm + OFF_STGB;
    float* s_bih  = sm + OFF_B;
    float* s_bhh  = sm + OFF_B + 24;

    const unsigned stgA_u = (unsigned)__cvta_generic_to_shared(s_stgA);
    const unsigned stgB_u = stgA_u + 32768u;

    const int tid  = threadIdx.x;
    const int lane = tid & 31;
    const int wid  = tid >> 5;
    const int team = wid >> 2;        // 0..3 (k-quarter)
    const int wj   = wid & 3;         // jl-pair 0..3; also posterior row
    const int bid  = blockIdx.x;
    const int j0g  = bid * JPB;
    const int s0g  = bid * SPB;
    const int jl0  = 2 * wj, jl1 = 2 * wj + 1;

    for (int v = tid; v < 24 * 256; v += TPB) {
        int row = v >> 8, c = v & 255;
        int jl = row / 3, g = row % 3;
        ((float4*)s_whh)[v] = ((const float4*)(W_hh + (size_t)(g * D_ + j0g + jl) * D_))[c];
    }
    for (int v = tid; v < 24 * 64; v += TPB) {
        int row = v >> 6, c = v & 63;
        int jl = row / 3, g = row % 3;
        ((float4*)s_wih)[v] = ((const float4*)(W_ih + (size_t)(g * D_ + j0g + jl) * S_))[c];
    }
    for (int v = tid; v < 4 * 256; v += TPB) {
        int row = v >> 8, c = v & 255;
        int sl = row >> 1, mv = row & 1;
        const float* W = (mv ? Wv : Wm) + (size_t)(s0g + sl) * (I_ + D_) + I_;
        ((float4*)s_wmvh)[v] = ((const float4*)W)[c];
    }
    if (tid < 24) {
        int jl = tid / 3, g = tid % 3;
        s_bih[tid] = b_ih[g * D_ + j0g + jl];
        s_bhh[tid] = b_hh[g * D_ + j0g + jl];
    }
    __syncthreads();

    // per-warp weight row base pointers
    const float* ihAr = s_wih + (jl0 * 3 + 0) * S_;
    const float* ihAz = s_wih + (jl0 * 3 + 1) * S_;
    const float* ihAn = s_wih + (jl0 * 3 + 2) * S_;
    const float* ihBr = s_wih + (jl1 * 3 + 0) * S_;
    const float* ihBz = s_wih + (jl1 * 3 + 1) * S_;
    const float* ihBn = s_wih + (jl1 * 3 + 2) * S_;
    const float* hhAr = s_whh + (jl0 * 3 + 0) * D_;
    const float* hhAz = s_whh + (jl0 * 3 + 1) * D_;
    const float* hhAn = s_whh + (jl0 * 3 + 2) * D_;
    const float* hhBr = s_whh + (jl1 * 3 + 0) * D_;
    const float* hhBz = s_whh + (jl1 * 3 + 1) * D_;
    const float* hhBn = s_whh + (jl1 * 3 + 2) * D_;
    const float* wpR  = s_wmvh + wj * D_;

    const float4* z4 = (const float4*)g_z;
    const float4* h4 = (const float4*)g_h;
    const int sboff = team * 2048 + 4 * lane;

    // carried: gh r/z (gi r/z added in), gh n-gate. Quarter partials.
    ull rA0 = 0, rA1 = 0, zA0 = 0, zA1 = 0, nA0 = 0, nA1 = 0;
    ull rB0 = 0, rB1 = 0, zB0 = 0, zB1 = 0, nB0 = 0, nB1 = 0;
    float hp0 = 0.f, hp1 = 0.f, hp2 = 0.f, hp3 = 0.f;
    ull du0, du1;

    cpa_z(stgA_u, z4); CP_COMMIT();      // z_{-1} = zeros

    for (int t = 0; t < T_; ++t) {
        float2 px = make_float2(0.f, 0.f);
        float nz = 0.f;
        if (tid < 128) {
            int slq = tid >> 6, bq = tid & 63;
            px = __ldcg((const float2*)(g_postx +
                    ((size_t)bq * T_ + t) * (2 * S_) + 2 * (s0g + slq)));
            nz = __ldcg(noise + ((size_t)t * B_ + bq) * S_ + s0g + slq);
        }

        // ===== (A) gi over z_{t-1}: both 32KB halves after ONE wait =====
        ull gA0 = 0, gA1 = 0, gB0 = 0, gB1 = 0;   // gi n-gate
        {
            CP_WAIT0(); __syncthreads();
            int off = team * 32;
            gchunk2<false>(s_stgA + sboff, ihAr + off, ihAz + off, ihAn + off,
                           ihBr + off, ihBz + off, ihBn + off, 0,
                           rA0, rA1, zA0, zA1, gA0, gA1,
                           rB0, rB1, zB0, zB1, gB0, gB1, du0, du1);
            off = 128 + team * 32;
            gchunk2<false>(s_stgB + sboff, ihAr + off, ihAz + off, ihAn + off,
                           ihBr + off, ihBz + off, ihBn + off, 0,
                           rA0, rA1, zA0, zA1, gA0, gA1,
                           rB0, rB1, zB0, zB1, gB0, gB1, du0, du1);
            __syncthreads();   // all warps done reading z before stgA reuse
        }

        // ---- finalize h_t: 4-way cross-team reduce (floats, stride 17) ----
        {
            if (team != 0) {
                float* r = s_stgA + ((team - 1) * 4 + wj) * 544 + lane * 17;
                r[0]  = sum2(rA0); r[1]  = sum2(rA1);
                r[2]  = sum2(zA0); r[3]  = sum2(zA1);
                r[4]  = sum2(gA0); r[5]  = sum2(gA1);
                r[6]  = sum2(nA0); r[7]  = sum2(nA1);
                r[8]  = sum2(rB0); r[9]  = sum2(rB1);
                r[10] = sum2(zB0); r[11] = sum2(zB1);
                r[12] = sum2(gB0); r[13] = sum2(gB1);
                r[14] = sum2(nB0); r[15] = sum2(nB1);
            }
            __syncthreads();
            if (team == 0) {
                float s[16];
                s[0]=sum2(rA0); s[1]=sum2(rA1); s[2]=sum2(zA0); s[3]=sum2(zA1);
                s[4]=sum2(gA0); s[5]=sum2(gA1); s[6]=sum2(nA0); s[7]=sum2(nA1);
                s[8]=sum2(rB0); s[9]=sum2(rB1); s[10]=sum2(zB0); s[11]=sum2(zB1);
                s[12]=sum2(gB0); s[13]=sum2(gB1); s[14]=sum2(nB0); s[15]=sum2(nB1);
#pragma unroll
                for (int tm = 0; tm < 3; ++tm) {
                    const float* r = s_stgA + (tm * 4 + wj) * 544 + lane * 17;
#pragma unroll
                    for (int q = 0; q < 16; ++q) s[q] += r[q];
                }
                float brA = s_bih[jl0*3+0] + s_bhh[jl0*3+0];
                float bzA = s_bih[jl0*3+1] + s_bhh[jl0*3+1];
                float biA = s_bih[jl0*3+2], bhA = s_bhh[jl0*3+2];
                float brB = s_bih[jl1*3+0] + s_bhh[jl1*3+0];
                float bzB = s_bih[jl1*3+1] + s_bhh[jl1*3+1];
                float biB = s_bih[jl1*3+2], bhB = s_bhh[jl1*3+2];

                float hnA0 = gru_cell(s[0]+brA, s[2]+bzA, s[4]+biA, s[6]+bhA, hp0);
                float hnA1 = gru_cell(s[1]+brA, s[3]+bzA, s[5]+biA, s[7]+bhA, hp1);
                float hnB0 = gru_cell(s[8]+brB, s[10]+bzB, s[12]+biB, s[14]+bhB, hp2);
                float hnB1 = gru_cell(s[9]+brB, s[11]+bzB, s[13]+biB, s[15]+bhB, hp3);
                hp0 = hnA0; hp1 = hnA1; hp2 = hnB0; hp3 = hnB1;

                int jp = (j0g >> 1) + wj;
                float4 hv = make_float4(hnA0, hnB0, hnA1, hnB1);
                __stcg((float4*)g_h + jp * 32 + lane, hv);
                __stcg((float2*)(g_rssm + ((size_t)(2*lane) * T_ + t) * R_ + j0g + jl0),
                       make_float2(hnA0, hnB0));
                __stcg((float2*)(g_rssm + ((size_t)(2*lane+1) * T_ + t) * R_ + j0g + jl0),
                       make_float2(hnA1, hnB1));
            }
            rA0 = 0; rA1 = 0; zA0 = 0; zA1 = 0; nA0 = 0; nA1 = 0;
            rB0 = 0; rB1 = 0; zB0 = 0; zB1 = 0; nB0 = 0; nB1 = 0;
        }

        grid_sync(2 * t + 1);
        cpa_chunk(stgA_u, h4); CP_COMMIT();      // h chunk 0 in flight

        // ===== (B) h-pass over h_t: gh_{t+1} + posterior row, 8 chunks =====
        ull P0 = 0, P1 = 0;
        for (int c = 0; c < 8; ++c) {
            CP_WAIT0(); __syncthreads();         // chunk c staged; buf(c-1) free
            if (c < 7) {
                cpa_chunk((c & 1) ? stgA_u : stgB_u, h4 + (c + 1) * 2048);
                CP_COMMIT();
            }
            const float* buf = (c & 1) ? s_stgB : s_stgA;
            int off = c * 128 + team * 32;
            gchunk2<true>(buf + sboff, hhAr + off, hhAz + off, hhAn + off,
                          hhBr + off, hhBz + off, hhBn + off, wpR + off,
                          rA0, rA1, zA0, zA1, nA0, nA1,
                          rB0, rB1, zB0, zB1, nB0, nB1, P0, P1);
        }

        // ---- finalize z_t: 16-piece posterior reduce ----
        {
            ull* red2 = (ull*)s_stgA;            // chunk7 lives in stgB
            *(ulonglong2*)(red2 + (size_t)(team * 4 + wj) * 64 + 2 * lane) =
                make_ulonglong2(P0, P1);
            __syncthreads();
            if (tid < 128) {
                int sl = tid >> 6, b = tid & 63;
                float m = px.x, v = px.y;
#pragma unroll
                for (int tm = 0; tm < 4; ++tm) {
                    m += sum2(red2[(size_t)(tm * 4 + 2 * sl) * 64 + b]);
                    v += sum2(red2[(size_t)(tm * 4 + 2 * sl + 1) * 64 + b]);
                }
                float zv = nz * __expf(0.5f * v) + m;
                int sg = s0g + sl;
                __stcg(&g_z[(size_t)(sg >> 1) * 128 + b * 2 + (sg & 1)], zv);
                g_rssm[((size_t)b * T_ + t) * R_ + D_ + sg] = zv;
            }
        }

        grid_sync(2 * t + 2);
        cpa_z(stgA_u, z4); CP_COMMIT();          // next step's z
    }
}

// ---------------------------------------------------------------------------
// Decoder GEMM, packed-f32x2, GK=32, double-buffered smem (unchanged).
// ---------------------------------------------------------------------------
#define GM 128
#define GN 64
#define GK 32
#define KK2 (GK / 2)

__global__ void __launch_bounds__(256, 2) gemm_f32x2_kernel(
    const float* __restrict__ A, const float* __restrict__ W,
    const float* __restrict__ bias, float* __restrict__ C,
    int M, int N, int K, int act)
{
    __shared__ ull As2[2][KK2][GM];
    __shared__ ull Ws2[2][KK2][GN];
    const int tid = threadIdx.x;
    const int bm = blockIdx.y * GM;
    const int bn = blockIdx.x * GN;
    const int tx = tid & 15, ty = tid >> 4;
    const int m0 = ty * 8, n0 = tx * 4;
    const int part = tid & 7;
    const int lrow = tid >> 3;

    ull acc[8][4];
#pragma unroll
    for (int i = 0; i < 8; ++i)
#pragma unroll
        for (int j = 0; j < 4; ++j) acc[i][j] = 0ULL;

    float4 va[4], vw[2];
#pragma unroll
    for (int i = 0; i < 4; ++i)
        va[i] = *(const float4*)(A + (size_t)(bm + lrow + i * 32) * K + part * 4);
#pragma unroll
    for (int i = 0; i < 2; ++i)
        vw[i] = *(const float4*)(W + (size_t)(bn + lrow + i * 32) * K + part * 4);

#pragma unroll
    for (int i = 0; i < 4; ++i) {
        As2[0][part * 2 + 0][lrow + i * 32] = packf2(va[i].x, va[i].y);
        As2[0][part * 2 + 1][lrow + i * 32] = packf2(va[i].z, va[i].w);
    }
#pragma unroll
    for (int i = 0; i < 2; ++i) {
        Ws2[0][part * 2 + 0][lrow + i * 32] = packf2(vw[i].x, vw[i].y);
        Ws2[0][part * 2 + 1][lrow + i * 32] = packf2(vw[i].z, vw[i].w);
    }

    const int niter = K / GK;
    int buf = 0;
    for (int kb = 0; kb < niter; ++kb) {
        __syncthreads();
        if (kb + 1 < niter) {
            int ko = (kb + 1) * GK + part * 4;
#pragma unroll
            for (int i = 0; i < 4; ++i)
                va[i] = *(const float4*)(A + (size_t)(bm + lrow + i * 32) * K + ko);
#pragma unroll
            for (int i = 0; i < 2; ++i)
                vw[i] = *(const float4*)(W + (size_t)(bn + lrow + i * 32) * K + ko);
        }
#pragma unroll
        for (int k2 = 0; k2 < KK2; ++k2) {
            ull ra[8], rw[4];
            *(ulonglong2*)&ra[0] = *(const ulonglong2*)&As2[buf][k2][m0 + 0];
            *(ulonglong2*)&ra[2] = *(const ulonglong2*)&As2[buf][k2][m0 + 2];
            *(ulonglong2*)&ra[4] = *(const ulonglong2*)&As2[buf][k2][m0 + 4];
            *(ulonglong2*)&ra[6] = *(const ulonglong2*)&As2[buf][k2][m0 + 6];
            *(ulonglong2*)&rw[0] = *(const ulonglong2*)&Ws2[buf][k2][n0 + 0];
            *(ulonglong2*)&rw[2] = *(const ulonglong2*)&Ws2[buf][k2][n0 + 2];
#pragma unroll
            for (int i = 0; i < 8; ++i)
#pragma unroll
                for (int j = 0; j < 4; ++j) ffma2(acc[i][j], ra[i], rw[j]);
        }
        if (kb + 1 < niter) {
            int nb = buf ^ 1;
#pragma unroll
            for (int i = 0; i < 4; ++i) {
                As2[nb][part * 2 + 0][lrow + i * 32] = packf2(va[i].x, va[i].y);
                As2[nb][part * 2 + 1][lrow + i * 32] = packf2(va[i].z, va[i].w);
            }
#pragma unroll
            for (int i = 0; i < 2; ++i) {
                Ws2[nb][part * 2 + 0][lrow + i * 32] = packf2(vw[i].x, vw[i].y);
                Ws2[nb][part * 2 + 1][lrow + i * 32] = packf2(vw[i].z, vw[i].w);
            }
            buf = nb;
        }
    }

    float bb[4];
#pragma unroll
    for (int j = 0; j < 4; ++j) bb[j] = bias[bn + n0 + j];
#pragma unroll
    for (int i = 0; i < 8; ++i) {
        float r[4];
#pragma unroll
        for (int j = 0; j < 4; ++j) {
            float v = sum2(acc[i][j]) + bb[j];
            r[j] = act ? (v > 0.f ? v : expm1f(v)) : v;
        }
        *(float4*)(C + (size_t)(bm + m0 + i) * N + bn + n0) =
            make_float4(r[0], r[1], r[2], r[3]);
    }
}

// ---------------------------------------------------------------------------
// Epilogue
// ---------------------------------------------------------------------------
__global__ void epilogue_kernel(const float* __restrict__ x, float* __restrict__ out) {
    size_t idx = (size_t)blockIdx.x * blockDim.x + threadIdx.x;
    const size_t total = (size_t)B_ * T_ * I_;
    if (idx >= total) return;
    int i = (int)(idx & (I_ - 1));
    size_t bt = idx >> 9;
    int t = (int)(bt & (T_ - 1));
    int b = (int)(bt >> 8);

    float xh;
    if (t == 0) xh = x[idx];
    else        xh = x[idx - I_] + g_dist[idx - I_];
    out[(size_t)B_ * (T_ - 1) * I_ + idx] = xh;

    if (t < T_ - 1)
        out[((size_t)b * (T_ - 1) + t) * I_ + i] = g_dist[idx];
}

// ---------------------------------------------------------------------------
// kernel_launch
// ---------------------------------------------------------------------------
extern "C" void kernel_launch(void* const* d_in, const int* in_sizes, int n_in,
                              void* d_out, int out_size) {
    const float* x     = (const float*)d_in[0];
    const float* noise = (const float*)d_in[1];
    const float* W_ih  = (const float*)d_in[2];
    const float* W_hh  = (const float*)d_in[3];
    const float* b_ih  = (const float*)d_in[4];
    const float* b_hh  = (const float*)d_in[5];
    const float* Wm    = (const float*)d_in[6];
    const float* bm    = (const float*)d_in[7];
    const float* Wv    = (const float*)d_in[8];
    const float* bv    = (const float*)d_in[9];
    const float* dW0   = (const float*)d_in[10];
    const float* db0   = (const float*)d_in[11];
    const float* dW1   = (const float*)d_in[12];
    const float* db1   = (const float*)d_in[13];
    const float* dW2   = (const float*)d_in[14];
    const float* db2   = (const float*)d_in[15];
    const float* dW3   = (const float*)d_in[16];
    const float* db3   = (const float*)d_in[17];
    float* out = (float*)d_out;

    cudaFuncSetAttribute(scan_kernel, cudaFuncAttributeMaxDynamicSharedMemorySize,
                         SCAN_SMEM_BYTES);

    void *p_rssm, *p_a0, *p_a1, *p_dist, *p_wx, *p_bx, *p_postx;
    cudaGetSymbolAddress(&p_rssm, g_rssm);
    cudaGetSymbolAddress(&p_a0, g_a0);
    cudaGetSymbolAddress(&p_a1, g_a1);
    cudaGetSymbolAddress(&p_dist, g_dist);
    cudaGetSymbolAddress(&p_wx, g_wx);
    cudaGetSymbolAddress(&p_bx, g_bx);
    cudaGetSymbolAddress(&p_postx, g_postx);

    const int M = B_ * T_;  // 16384

    init_state_kernel<<<64, 256>>>();
    build_wx_kernel<<<2 * S_, 256>>>(Wm, Wv, bm, bv);

    gemm_f32x2_kernel<<<dim3((2 * S_) / GN, M / GM), 256>>>(
        x, (const float*)p_wx, (const float*)p_bx, (float*)p_postx,
        M, 2 * S_, I_, 0);

    scan_kernel<<<GBLK, TPB, SCAN_SMEM_BYTES>>>(W_ih, W_hh, b_ih, b_hh,
                                                Wm, Wv, noise);

    gemm_f32x2_kernel<<<dim3(H_ / GN, M / GM), 256>>>(
        (const float*)p_rssm, dW0, db0, (float*)p_a0, M, H_, R_, 1);
    gemm_f32x2_kernel<<<dim3(H_ / GN, M / GM), 256>>>(
        (const float*)p_a0, dW1, db1, (float*)p_a1, M, H_, H_, 1);
    gemm_f32x2_kernel<<<dim3(H_ / GN, M / GM), 256>>>(
        (const float*)p_a1, dW2, db2, (float*)p_a0, M, H_, H_, 1);
    gemm_f32x2_kernel<<<dim3(I_ / GN, M / GM), 256>>>(
        (const float*)p_a0, dW3, db3, (float*)p_dist, M, I_, H_, 0);

    epilogue_kernel<<<(B_ * T_ * I_ + 255) / 256, 256>>>(x, out);
}

// round 13
// speedup vs baseline: 1.4779x; 1.0057x over previous
#include <cuda_runtime.h>
#include <math.h>

// ---------------------------------------------------------------------------
// Problem dims
// ---------------------------------------------------------------------------
#define B_ 64
#define T_ 256
#define I_ 512
#define S_ 256
#define D_ 1024
#define H_ 1024
#define R_ 1280          // D_ + S_

#define GBLK 128         // persistent blocks; 1 block/SM, all co-resident
#define TPB  512         // 16 warps: 4 k-teams x 4 jl-pair warps
#define JPB  8
#define SPB  2

typedef unsigned long long ull;

// Scan shared memory layout (floats)
#define N_WHH  (24 * 1024)
#define N_WIH  (24 * 256)
#define N_WMVH (4 * 1024)
#define OFF_WIH   (N_WHH)
#define OFF_WMVH  (OFF_WIH + N_WIH)
#define OFF_STG   (OFF_WMVH + N_WMVH)        // 4 teams x 2 bufs x 2048 floats
#define OFF_B     (OFF_STG + 16384)
#define SCAN_SMEM_FLOATS (OFF_B + 64)
#define SCAN_SMEM_BYTES  (SCAN_SMEM_FLOATS * 4)   // 205,056 B

// ---------------------------------------------------------------------------
// Device-global scratch. Activations (h, z) use k-PAIRED batch-last layout:
//   element (k, b) at float offset (k>>1)*128 + b*2 + (k&1)
// ---------------------------------------------------------------------------
__device__ __align__(256) float g_h[D_ * B_];
__device__ __align__(256) float g_z[S_ * B_];
__device__ __align__(256) float g_wx[2 * S_ * I_];
__device__ __align__(256) float g_bx[2 * S_];
__device__ __align__(256) float g_postx[(size_t)B_ * T_ * 2 * S_];
__device__ __align__(256) float g_rssm[(size_t)B_ * T_ * R_];
__device__ __align__(256) float g_a0[(size_t)B_ * T_ * H_];
__device__ __align__(256) float g_a1[(size_t)B_ * T_ * H_];
__device__ __align__(256) float g_dist[(size_t)B_ * T_ * I_];

__device__ unsigned g_arrive[GBLK * 32];
__device__ unsigned g_release;

// ---------------------------------------------------------------------------
// Packed-f32x2 helpers
// ---------------------------------------------------------------------------
__device__ __forceinline__ void ffma2(ull& d, ull a, ull b) {
    asm("fma.rn.f32x2 %0, %1, %2, %0;" : "+l"(d) : "l"(a), "l"(b));
}
__device__ __forceinline__ float sum2(ull v) {
    return __uint_as_float((unsigned)v) + __uint_as_float((unsigned)(v >> 32));
}
__device__ __forceinline__ ull packf2(float lo, float hi) {
    return (ull)__float_as_uint(lo) | ((ull)__float_as_uint(hi) << 32);
}

// ---------------------------------------------------------------------------
// cp.async helpers + named team barrier
// ---------------------------------------------------------------------------
__device__ __forceinline__ void cpa16(unsigned dst, const void* src) {
    asm volatile("cp.async.cg.shared.global [%0], [%1], 16;" :: "r"(dst), "l"(src));
}
#define CP_COMMIT() asm volatile("cp.async.commit_group;" ::: "memory")
#define CP_WAIT0()  asm volatile("cp.async.wait_group 0;" ::: "memory")

// team (128 threads) stages its 8KB quarter: 512 float4, 4 per thread
__device__ __forceinline__ void cpa_team(unsigned dstu, const float4* src, int ttid) {
#pragma unroll
    for (int i = 0; i < 4; ++i)
        cpa16(dstu + (unsigned)((ttid + i * 128) * 16), src + ttid + i * 128);
}
__device__ __forceinline__ void teambar(int team) {
    asm volatile("bar.sync %0, 128;" :: "r"(team + 1) : "memory");
}

// ---------------------------------------------------------------------------
// Grid barrier
// ---------------------------------------------------------------------------
__device__ __forceinline__ void grid_sync(unsigned token) {
    __syncthreads();
    if (blockIdx.x == 0) {
        if (threadIdx.x > 0 && threadIdx.x < GBLK) {
            unsigned v;
            do {
                asm volatile("ld.acquire.gpu.global.u32 %0, [%1];"
                             : "=r"(v) : "l"(g_arrive + threadIdx.x * 32) : "memory");
            } while (v < token);
        }
        __syncthreads();
        if (threadIdx.x == 0) {
            asm volatile("st.release.gpu.global.u32 [%0], %1;"
                         :: "l"(&g_release), "r"(token) : "memory");
        }
    } else {
        if (threadIdx.x == 0) {
            asm volatile("st.release.gpu.global.u32 [%0], %1;"
                         :: "l"(g_arrive + blockIdx.x * 32), "r"(token) : "memory");
            unsigned v;
            do {
                asm volatile("ld.acquire.gpu.global.u32 %0, [%1];"
                             : "=r"(v) : "l"(&g_release) : "memory");
            } while (v < token);
        }
        __syncthreads();
    }
}

// ---------------------------------------------------------------------------
// One warp's quarter-chunk inner product: 6 GRU rows (2 jl) + optional
// posterior row. 2 batches per lane, 32 k (16 k-pair rows in team buffer).
// ---------------------------------------------------------------------------
template<bool POST>
__device__ __forceinline__ void gchunk2(const float* __restrict__ sb,
        const float* __restrict__ ar, const float* __restrict__ az,
        const float* __restrict__ an,
        const float* __restrict__ br, const float* __restrict__ bz,
        const float* __restrict__ bn,
        const float* __restrict__ wp,
        ull& rA0, ull& rA1, ull& zA0, ull& zA1, ull& nA0, ull& nA1,
        ull& rB0, ull& rB1, ull& zB0, ull& zB1, ull& nB0, ull& nB1,
        ull& P0, ull& P1)
{
#pragma unroll
    for (int i = 0; i < 8; ++i) {
        ulonglong2 a0 = *(const ulonglong2*)(sb + (2 * i) * 128);
        ulonglong2 a1 = *(const ulonglong2*)(sb + (2 * i + 1) * 128);
        ulonglong2 q;
        q = *(const ulonglong2*)(ar + 4 * i);
        ffma2(rA0, q.x, a0.x); ffma2(rA0, q.y, a1.x);
        ffma2(rA1, q.x, a0.y); ffma2(rA1, q.y, a1.y);
        q = *(const ulonglong2*)(az + 4 * i);
        ffma2(zA0, q.x, a0.x); ffma2(zA0, q.y, a1.x);
        ffma2(zA1, q.x, a0.y); ffma2(zA1, q.y, a1.y);
        q = *(const ulonglong2*)(an + 4 * i);
        ffma2(nA0, q.x, a0.x); ffma2(nA0, q.y, a1.x);
        ffma2(nA1, q.x, a0.y); ffma2(nA1, q.y, a1.y);
        q = *(const ulonglong2*)(br + 4 * i);
        ffma2(rB0, q.x, a0.x); ffma2(rB0, q.y, a1.x);
        ffma2(rB1, q.x, a0.y); ffma2(rB1, q.y, a1.y);
        q = *(const ulonglong2*)(bz + 4 * i);
        ffma2(zB0, q.x, a0.x); ffma2(zB0, q.y, a1.x);
        ffma2(zB1, q.x, a0.y); ffma2(zB1, q.y, a1.y);
        q = *(const ulonglong2*)(bn + 4 * i);
        ffma2(nB0, q.x, a0.x); ffma2(nB0, q.y, a1.x);
        ffma2(nB1, q.x, a0.y); ffma2(nB1, q.y, a1.y);
        if (POST) {
            q = *(const ulonglong2*)(wp + 4 * i);
            ffma2(P0, q.x, a0.x); ffma2(P0, q.y, a1.x);
            ffma2(P1, q.x, a0.y); ffma2(P1, q.y, a1.y);
        }
    }
}

__device__ __forceinline__ float gru_cell(float vr, float vz, float gi,
                                          float gh, float hp) {
    float r = 1.f / (1.f + __expf(-vr));
    float z = 1.f / (1.f + __expf(-vz));
    float n = tanhf(gi + r * gh);
    return (1.f - z) * n + z * hp;
}

__global__ void init_state_kernel() {
    const int idx = blockIdx.x * blockDim.x + threadIdx.x;
    const int stride = gridDim.x * blockDim.x;
    for (int i = idx; i < D_ * B_; i += stride) g_h[i] = 0.f;
    for (int i = idx; i < S_ * B_; i += stride) g_z[i] = 0.f;
    for (int i = idx; i < GBLK * 32; i += stride) g_arrive[i] = 0u;
    if (idx == 0) g_release = 0u;
}

__global__ void build_wx_kernel(const float* __restrict__ Wm,
                                const float* __restrict__ Wv,
                                const float* __restrict__ bm,
                                const float* __restrict__ bv) {
    const int n = blockIdx.x;
    const int s = n >> 1, mv = n & 1;
    const float* src = (mv ? Wv : Wm) + (size_t)s * (I_ + D_);
    float* dst = g_wx + (size_t)n * I_;
    for (int k = threadIdx.x; k < I_; k += blockDim.x) dst[k] = src[k];
    if (threadIdx.x == 0) g_bx[n] = mv ? bv[s] : bm[s];
}

// ---------------------------------------------------------------------------
// Persistent scan: 4 k-teams x 4 warps; per-team autonomous cp.async staging
// with named team barriers (no per-chunk block-wide syncs).
// ---------------------------------------------------------------------------
__global__ void __launch_bounds__(TPB, 1) scan_kernel(
    const float* __restrict__ W_ih, const float* __restrict__ W_hh,
    const float* __restrict__ b_ih, const float* __restrict__ b_hh,
    const float* __restrict__ Wm,   const float* __restrict__ Wv,
    const float* __restrict__ noise)
{
    extern __shared__ float sm[];
    float* s_whh  = sm;
    float* s_wih  = sm + OFF_WIH;
    float* s_wmvh = sm + OFF_WMVH;
    float* s_stg  = sm + OFF_STG;
    float* s_bih  = sm + OFF_B;
    float* s_bhh  = sm + OFF_B + 24;

    const unsigned stg_u = (unsigned)__cvta_generic_to_shared(s_stg);

    const int tid  = threadIdx.x;
    const int lane = tid & 31;
    const int wid  = tid >> 5;
    const int team = wid >> 2;        // 0..3 (k-quarter); threads contiguous
    const int ttid = tid & 127;       // thread id within team
    const int wj   = wid & 3;         // jl-pair 0..3; also posterior row
    const int bid  = blockIdx.x;
    const int j0g  = bid * JPB;
    const int s0g  = bid * SPB;
    const int jl0  = 2 * wj, jl1 = 2 * wj + 1;

    for (int v = tid; v < 24 * 256; v += TPB) {
        int row = v >> 8, c = v & 255;
        int jl = row / 3, g = row % 3;
        ((float4*)s_whh)[v] = ((const float4*)(W_hh + (size_t)(g * D_ + j0g + jl) * D_))[c];
    }
    for (int v = tid; v < 24 * 64; v += TPB) {
        int row = v >> 6, c = v & 63;
        int jl = row / 3, g = row % 3;
        ((float4*)s_wih)[v] = ((const float4*)(W_ih + (size_t)(g * D_ + j0g + jl) * S_))[c];
    }
    for (int v = tid; v < 4 * 256; v += TPB) {
        int row = v >> 8, c = v & 255;
        int sl = row >> 1, mv = row & 1;
        const float* W = (mv ? Wv : Wm) + (size_t)(s0g + sl) * (I_ + D_) + I_;
        ((float4*)s_wmvh)[v] = ((const float4*)W)[c];
    }
    if (tid < 24) {
        int jl = tid / 3, g = tid % 3;
        s_bih[tid] = b_ih[g * D_ + j0g + jl];
        s_bhh[tid] = b_hh[g * D_ + j0g + jl];
    }
    __syncthreads();

    // per-warp weight row base pointers
    const float* ihAr = s_wih + (jl0 * 3 + 0) * S_;
    const float* ihAz = s_wih + (jl0 * 3 + 1) * S_;
    const float* ihAn = s_wih + (jl0 * 3 + 2) * S_;
    const float* ihBr = s_wih + (jl1 * 3 + 0) * S_;
    const float* ihBz = s_wih + (jl1 * 3 + 1) * S_;
    const float* ihBn = s_wih + (jl1 * 3 + 2) * S_;
    const float* hhAr = s_whh + (jl0 * 3 + 0) * D_;
    const float* hhAz = s_whh + (jl0 * 3 + 1) * D_;
    const float* hhAn = s_whh + (jl0 * 3 + 2) * D_;
    const float* hhBr = s_whh + (jl1 * 3 + 0) * D_;
    const float* hhBz = s_whh + (jl1 * 3 + 1) * D_;
    const float* hhBn = s_whh + (jl1 * 3 + 2) * D_;
    const float* wpR  = s_wmvh + wj * D_;

    // per-team staging buffers (2048 floats each) and sources
    const unsigned tb0 = stg_u + (unsigned)team * 16384u;
    const unsigned tb1 = tb0 + 8192u;
    const float* sb0 = s_stg + team * 4096 + 4 * lane;
    const float* sb1 = sb0 + 2048;
    const float4* zsrc = (const float4*)g_z + team * 512;
    const float4* hsrc = (const float4*)g_h + team * 512;

    // carried accumulators (quarter partials)
    ull rA0 = 0, rA1 = 0, zA0 = 0, zA1 = 0, nA0 = 0, nA1 = 0;
    ull rB0 = 0, rB1 = 0, zB0 = 0, zB1 = 0, nB0 = 0, nB1 = 0;
    float hp0 = 0.f, hp1 = 0.f, hp2 = 0.f, hp3 = 0.f;
    ull du0, du1;

    cpa_team(tb0, zsrc, ttid); CP_COMMIT();      // z_{-1} quarter 0

    for (int t = 0; t < T_; ++t) {
        float2 px = make_float2(0.f, 0.f);
        float nz = 0.f;
        if (tid < 128) {
            int slq = tid >> 6, bq = tid & 63;
            px = __ldcg((const float2*)(g_postx +
                    ((size_t)bq * T_ + t) * (2 * S_) + 2 * (s0g + slq)));
            nz = __ldcg(noise + ((size_t)t * B_ + bq) * S_ + s0g + slq);
        }

        // ===== (A) gi over z_{t-1}: 2 team-quarter chunks =====
        ull gA0 = 0, gA1 = 0, gB0 = 0, gB1 = 0;   // gi n-gate
        {
            CP_WAIT0(); teambar(team);
            cpa_team(tb1, zsrc + 2048, ttid); CP_COMMIT();
            int off = team * 32;
            gchunk2<false>(sb0, ihAr + off, ihAz + off, ihAn + off,
                           ihBr + off, ihBz + off, ihBn + off, 0,
                           rA0, rA1, zA0, zA1, gA0, gA1,
                           rB0, rB1, zB0, zB1, gB0, gB1, du0, du1);
            CP_WAIT0(); teambar(team);
            off = 128 + team * 32;
            gchunk2<false>(sb1, ihAr + off, ihAz + off, ihAn + off,
                           ihBr + off, ihBz + off, ihBn + off, 0,
                           rA0, rA1, zA0, zA1, gA0, gA1,
                           rB0, rB1, zB0, zB1, gB0, gB1, du0, du1);
        }

        // ---- finalize h_t: 4-way cross-team reduce (floats, stride 17) ----
        {
            __syncthreads();    // all teams done reading staging buffers
            if (team != 0) {
                float* r = s_stg + ((team - 1) * 4 + wj) * 544 + lane * 17;
                r[0]  = sum2(rA0); r[1]  = sum2(rA1);
                r[2]  = sum2(zA0); r[3]  = sum2(zA1);
                r[4]  = sum2(gA0); r[5]  = sum2(gA1);
                r[6]  = sum2(nA0); r[7]  = sum2(nA1);
                r[8]  = sum2(rB0); r[9]  = sum2(rB1);
                r[10] = sum2(zB0); r[11] = sum2(zB1);
                r[12] = sum2(gB0); r[13] = sum2(gB1);
                r[14] = sum2(nB0); r[15] = sum2(nB1);
            }
            __syncthreads();
            if (team == 0) {
                float s[16];
                s[0]=sum2(rA0); s[1]=sum2(rA1); s[2]=sum2(zA0); s[3]=sum2(zA1);
                s[4]=sum2(gA0); s[5]=sum2(gA1); s[6]=sum2(nA0); s[7]=sum2(nA1);
                s[8]=sum2(rB0); s[9]=sum2(rB1); s[10]=sum2(zB0); s[11]=sum2(zB1);
                s[12]=sum2(gB0); s[13]=sum2(gB1); s[14]=sum2(nB0); s[15]=sum2(nB1);
#pragma unroll
                for (int tm = 0; tm < 3; ++tm) {
                    const float* r = s_stg + (tm * 4 + wj) * 544 + lane * 17;
#pragma unroll
                    for (int q = 0; q < 16; ++q) s[q] += r[q];
                }
                float brA = s_bih[jl0*3+0] + s_bhh[jl0*3+0];
                float bzA = s_bih[jl0*3+1] + s_bhh[jl0*3+1];
                float biA = s_bih[jl0*3+2], bhA = s_bhh[jl0*3+2];
                float brB = s_bih[jl1*3+0] + s_bhh[jl1*3+0];
                float bzB = s_bih[jl1*3+1] + s_bhh[jl1*3+1];
                float biB = s_bih[jl1*3+2], bhB = s_bhh[jl1*3+2];

                float hnA0 = gru_cell(s[0]+brA, s[2]+bzA, s[4]+biA, s[6]+bhA, hp0);
                float hnA1 = gru_cell(s[1]+brA, s[3]+bzA, s[5]+biA, s[7]+bhA, hp1);
                float hnB0 = gru_cell(s[8]+brB, s[10]+bzB, s[12]+biB, s[14]+bhB, hp2);
                float hnB1 = gru_cell(s[9]+brB, s[11]+bzB, s[13]+biB, s[15]+bhB, hp3);
                hp0 = hnA0; hp1 = hnA1; hp2 = hnB0; hp3 = hnB1;

                int jp = (j0g >> 1) + wj;
                float4 hv = make_float4(hnA0, hnB0, hnA1, hnB1);
                __stcg((float4*)g_h + jp * 32 + lane, hv);
                __stcg((float2*)(g_rssm + ((size_t)(2*lane) * T_ + t) * R_ + j0g + jl0),
                       make_float2(hnA0, hnB0));
                __stcg((float2*)(g_rssm + ((size_t)(2*lane+1) * T_ + t) * R_ + j0g + jl0),
                       make_float2(hnA1, hnB1));
            }
            rA0 = 0; rA1 = 0; zA0 = 0; zA1 = 0; nA0 = 0; nA1 = 0;
            rB0 = 0; rB1 = 0; zB0 = 0; zB1 = 0; nB0 = 0; nB1 = 0;
        }

        grid_sync(2 * t + 1);
        cpa_team(tb0, hsrc, ttid); CP_COMMIT();      // h chunk 0 quarter

        // ===== (B) h-pass over h_t: 8 team-quarter chunks, team-local sync ====
        ull P0 = 0, P1 = 0;
        for (int c = 0; c < 8; ++c) {
            CP_WAIT0(); teambar(team);               // chunk c landed, c-1 reads done
            if (c < 7) {
                cpa_team((c & 1) ? tb0 : tb1, hsrc + (c + 1) * 2048, ttid);
                CP_COMMIT();
            }
            const float* buf = (c & 1) ? sb1 : sb0;
            int off = c * 128 + team * 32;
            gchunk2<true>(buf, hhAr + off, hhAz + off, hhAn + off,
                          hhBr + off, hhBz + off, hhBn + off, wpR + off,
                          rA0, rA1, zA0, zA1, nA0, nA1,
                          rB0, rB1, zB0, zB1, nB0, nB1, P0, P1);
        }

        // ---- finalize z_t: 16-piece posterior reduce ----
        {
            __syncthreads();    // all teams done with staging buffers
            ull* red2 = (ull*)s_stg;
            *(ulonglong2*)(red2 + (size_t)(team * 4 + wj) * 64 + 2 * lane) =
                make_ulonglong2(P0, P1);
            __syncthreads();
            if (tid < 128) {
                int sl = tid >> 6, b = tid & 63;
                float m = px.x, v = px.y;
#pragma unroll
                for (int tm = 0; tm < 4; ++tm) {
                    m += sum2(red2[(size_t)(tm * 4 + 2 * sl) * 64 + b]);
                    v += sum2(red2[(size_t)(tm * 4 + 2 * sl + 1) * 64 + b]);
                }
                float zv = nz * __expf(0.5f * v) + m;
                int sg = s0g + sl;
                __stcg(&g_z[(size_t)(sg >> 1) * 128 + b * 2 + (sg & 1)], zv);
                g_rssm[((size_t)b * T_ + t) * R_ + D_ + sg] = zv;
            }
        }

        grid_sync(2 * t + 2);
        cpa_team(tb0, zsrc, ttid); CP_COMMIT();      // next step's z quarter 0
    }
}

// ---------------------------------------------------------------------------
// Decoder GEMM, packed-f32x2, GK=32, double-buffered smem (unchanged).
// ---------------------------------------------------------------------------
#define GM 128
#define GN 64
#define GK 32
#define KK2 (GK / 2)

__global__ void __launch_bounds__(256, 2) gemm_f32x2_kernel(
    const float* __restrict__ A, const float* __restrict__ W,
    const float* __restrict__ bias, float* __restrict__ C,
    int M, int N, int K, int act)
{
    __shared__ ull As2[2][KK2][GM];
    __shared__ ull Ws2[2][KK2][GN];
    const int tid = threadIdx.x;
    const int bm = blockIdx.y * GM;
    const int bn = blockIdx.x * GN;
    const int tx = tid & 15, ty = tid >> 4;
    const int m0 = ty * 8, n0 = tx * 4;
    const int part = tid & 7;
    const int lrow = tid >> 3;

    ull acc[8][4];
#pragma unroll
    for (int i = 0; i < 8; ++i)
#pragma unroll
        for (int j = 0; j < 4; ++j) acc[i][j] = 0ULL;

    float4 va[4], vw[2];
#pragma unroll
    for (int i = 0; i < 4; ++i)
        va[i] = *(const float4*)(A + (size_t)(bm + lrow + i * 32) * K + part * 4);
#pragma unroll
    for (int i = 0; i < 2; ++i)
        vw[i] = *(const float4*)(W + (size_t)(bn + lrow + i * 32) * K + part * 4);

#pragma unroll
    for (int i = 0; i < 4; ++i) {
        As2[0][part * 2 + 0][lrow + i * 32] = packf2(va[i].x, va[i].y);
        As2[0][part * 2 + 1][lrow + i * 32] = packf2(va[i].z, va[i].w);
    }
#pragma unroll
    for (int i = 0; i < 2; ++i) {
        Ws2[0][part * 2 + 0][lrow + i * 32] = packf2(vw[i].x, vw[i].y);
        Ws2[0][part * 2 + 1][lrow + i * 32] = packf2(vw[i].z, vw[i].w);
    }

    const int niter = K / GK;
    int buf = 0;
    for (int kb = 0; kb < niter; ++kb) {
        __syncthreads();
        if (kb + 1 < niter) {
            int ko = (kb + 1) * GK + part * 4;
#pragma unroll
            for (int i = 0; i < 4; ++i)
                va[i] = *(const float4*)(A + (size_t)(bm + lrow + i * 32) * K + ko);
#pragma unroll
            for (int i = 0; i < 2; ++i)
                vw[i] = *(const float4*)(W + (size_t)(bn + lrow + i * 32) * K + ko);
        }
#pragma unroll
        for (int k2 = 0; k2 < KK2; ++k2) {
            ull ra[8], rw[4];
            *(ulonglong2*)&ra[0] = *(const ulonglong2*)&As2[buf][k2][m0 + 0];
            *(ulonglong2*)&ra[2] = *(const ulonglong2*)&As2[buf][k2][m0 + 2];
            *(ulonglong2*)&ra[4] = *(const ulonglong2*)&As2[buf][k2][m0 + 4];
            *(ulonglong2*)&ra[6] = *(const ulonglong2*)&As2[buf][k2][m0 + 6];
            *(ulonglong2*)&rw[0] = *(const ulonglong2*)&Ws2[buf][k2][n0 + 0];
            *(ulonglong2*)&rw[2] = *(const ulonglong2*)&Ws2[buf][k2][n0 + 2];
#pragma unroll
            for (int i = 0; i < 8; ++i)
#pragma unroll
                for (int j = 0; j < 4; ++j) ffma2(acc[i][j], ra[i], rw[j]);
        }
        if (kb + 1 < niter) {
            int nb = buf ^ 1;
#pragma unroll
            for (int i = 0; i < 4; ++i) {
                As2[nb][part * 2 + 0][lrow + i * 32] = packf2(va[i].x, va[i].y);
                As2[nb][part * 2 + 1][lrow + i * 32] = packf2(va[i].z, va[i].w);
            }
#pragma unroll
            for (int i = 0; i < 2; ++i) {
                Ws2[nb][part * 2 + 0][lrow + i * 32] = packf2(vw[i].x, vw[i].y);
                Ws2[nb][part * 2 + 1][lrow + i * 32] = packf2(vw[i].z, vw[i].w);
            }
            buf = nb;
        }
    }

    float bb[4];
#pragma unroll
    for (int j = 0; j < 4; ++j) bb[j] = bias[bn + n0 + j];
#pragma unroll
    for (int i = 0; i < 8; ++i) {
        float r[4];
#pragma unroll
        for (int j = 0; j < 4; ++j) {
            float v = sum2(acc[i][j]) + bb[j];
            r[j] = act ? (v > 0.f ? v : expm1f(v)) : v;
        }
        *(float4*)(C + (size_t)(bm + m0 + i) * N + bn + n0) =
            make_float4(r[0], r[1], r[2], r[3]);
    }
}

// ---------------------------------------------------------------------------
// Epilogue
// ---------------------------------------------------------------------------
__global__ void epilogue_kernel(const float* __restrict__ x, float* __restrict__ out) {
    size_t idx = (size_t)blockIdx.x * blockDim.x + threadIdx.x;
    const size_t total = (size_t)B_ * T_ * I_;
    if (idx >= total) return;
    int i = (int)(idx & (I_ - 1));
    size_t bt = idx >> 9;
    int t = (int)(bt & (T_ - 1));
    int b = (int)(bt >> 8);

    float xh;
    if (t == 0) xh = x[idx];
    else        xh = x[idx - I_] + g_dist[idx - I_];
    out[(size_t)B_ * (T_ - 1) * I_ + idx] = xh;

    if (t < T_ - 1)
        out[((size_t)b * (T_ - 1) + t) * I_ + i] = g_dist[idx];
}

// ---------------------------------------------------------------------------
// kernel_launch
// ---------------------------------------------------------------------------
extern "C" void kernel_launch(void* const* d_in, const int* in_sizes, int n_in,
                              void* d_out, int out_size) {
    const float* x     = (const float*)d_in[0];
    const float* noise = (const float*)d_in[1];
    const float* W_ih  = (const float*)d_in[2];
    const float* W_hh  = (const float*)d_in[3];
    const float* b_ih  = (const float*)d_in[4];
    const float* b_hh  = (const float*)d_in[5];
    const float* Wm    = (const float*)d_in[6];
    const float* bm    = (const float*)d_in[7];
    const float* Wv    = (const float*)d_in[8];
    const float* bv    = (const float*)d_in[9];
    const float* dW0   = (const float*)d_in[10];
    const float* db0   = (const float*)d_in[11];
    const float* dW1   = (const float*)d_in[12];
    const float* db1   = (const float*)d_in[13];
    const float* dW2   = (const float*)d_in[14];
    const float* db2   = (const float*)d_in[15];
    const float* dW3   = (const float*)d_in[16];
    const float* db3   = (const float*)d_in[17];
    float* out = (float*)d_out;

    cudaFuncSetAttribute(scan_kernel, cudaFuncAttributeMaxDynamicSharedMemorySize,
                         SCAN_SMEM_BYTES);

    void *p_rssm, *p_a0, *p_a1, *p_dist, *p_wx, *p_bx, *p_postx;
    cudaGetSymbolAddress(&p_rssm, g_rssm);
    cudaGetSymbolAddress(&p_a0, g_a0);
    cudaGetSymbolAddress(&p_a1, g_a1);
    cudaGetSymbolAddress(&p_dist, g_dist);
    cudaGetSymbolAddress(&p_wx, g_wx);
    cudaGetSymbolAddress(&p_bx, g_bx);
    cudaGetSymbolAddress(&p_postx, g_postx);

    const int M = B_ * T_;  // 16384

    init_state_kernel<<<64, 256>>>();
    build_wx_kernel<<<2 * S_, 256>>>(Wm, Wv, bm, bv);

    gemm_f32x2_kernel<<<dim3((2 * S_) / GN, M / GM), 256>>>(
        x, (const float*)p_wx, (const float*)p_bx, (float*)p_postx,
        M, 2 * S_, I_, 0);

    scan_kernel<<<GBLK, TPB, SCAN_SMEM_BYTES>>>(W_ih, W_hh, b_ih, b_hh,
                                                Wm, Wv, noise);

    gemm_f32x2_kernel<<<dim3(H_ / GN, M / GM), 256>>>(
        (const float*)p_rssm, dW0, db0, (float*)p_a0, M, H_, R_, 1);
    gemm_f32x2_kernel<<<dim3(H_ / GN, M / GM), 256>>>(
        (const float*)p_a0, dW1, db1, (float*)p_a1, M, H_, H_, 1);
    gemm_f32x2_kernel<<<dim3(H_ / GN, M / GM), 256>>>(
        (const float*)p_a1, dW2, db2, (float*)p_a0, M, H_, H_, 1);
    gemm_f32x2_kernel<<<dim3(I_ / GN, M / GM), 256>>>(
        (const float*)p_a0, dW3, db3, (float*)p_dist, M, I_, H_, 0);

    epilogue_kernel<<<(B_ * T_ * I_ + 255) / 256, 256>>>(x, out);
}

// round 14
// speedup vs baseline: 1.4824x; 1.0030x over previous
#include <cuda_runtime.h>
#include <math.h>

// ---------------------------------------------------------------------------
// Problem dims
// ---------------------------------------------------------------------------
#define B_ 64
#define T_ 256
#define I_ 512
#define S_ 256
#define D_ 1024
#define H_ 1024
#define R_ 1280          // D_ + S_

#define GBLK 128         // persistent blocks; 1 block/SM, all co-resident
#define TPB  512         // 16 warps: 4 k-teams x 4 jl-pair warps
#define JPB  8
#define SPB  2

typedef unsigned long long ull;

// Scan shared memory layout (floats)
#define N_WHH  (24 * 1024)
#define N_WIH  (24 * 256)
#define N_WMVH (4 * 1024)
#define OFF_WIH   (N_WHH)
#define OFF_WMVH  (OFF_WIH + N_WIH)
#define OFF_STG   (OFF_WMVH + N_WMVH)        // 4 teams x 2 bufs x 2048 floats
#define OFF_B     (OFF_STG + 16384)
#define SCAN_SMEM_FLOATS (OFF_B + 64)
#define SCAN_SMEM_BYTES  (SCAN_SMEM_FLOATS * 4)   // 205,056 B

// ---------------------------------------------------------------------------
// Device-global scratch. Activations (h, z) use k-PAIRED batch-last layout:
//   element (k, b) at float offset (k>>1)*128 + b*2 + (k&1)
// ---------------------------------------------------------------------------
__device__ __align__(256) float g_h[D_ * B_];
__device__ __align__(256) float g_z[S_ * B_];
__device__ __align__(256) float g_wx[2 * S_ * I_];
__device__ __align__(256) float g_bx[2 * S_];
__device__ __align__(256) float g_postx[(size_t)B_ * T_ * 2 * S_];
__device__ __align__(256) float g_rssm[(size_t)B_ * T_ * R_];
__device__ __align__(256) float g_a0[(size_t)B_ * T_ * H_];
__device__ __align__(256) float g_a1[(size_t)B_ * T_ * H_];
__device__ __align__(256) float g_dist[(size_t)B_ * T_ * I_];

__device__ unsigned g_arrive[GBLK * 32];
__device__ unsigned g_release;

// ---------------------------------------------------------------------------
// Packed-f32x2 helpers
// ---------------------------------------------------------------------------
__device__ __forceinline__ void ffma2(ull& d, ull a, ull b) {
    asm("fma.rn.f32x2 %0, %1, %2, %0;" : "+l"(d) : "l"(a), "l"(b));
}
__device__ __forceinline__ float sum2(ull v) {
    return __uint_as_float((unsigned)v) + __uint_as_float((unsigned)(v >> 32));
}
__device__ __forceinline__ ull packf2(float lo, float hi) {
    return (ull)__float_as_uint(lo) | ((ull)__float_as_uint(hi) << 32);
}

// ---------------------------------------------------------------------------
// cp.async helpers + named team barrier
// ---------------------------------------------------------------------------
__device__ __forceinline__ void cpa16(unsigned dst, const void* src) {
    asm volatile("cp.async.cg.shared.global [%0], [%1], 16;" :: "r"(dst), "l"(src));
}
#define CP_COMMIT() asm volatile("cp.async.commit_group;" ::: "memory")
#define CP_WAIT0()  asm volatile("cp.async.wait_group 0;" ::: "memory")

// team (128 threads) stages its 8KB quarter: 512 float4, 4 per thread
__device__ __forceinline__ void cpa_team(unsigned dstu, const float4* src, int ttid) {
#pragma unroll
    for (int i = 0; i < 4; ++i)
        cpa16(dstu + (unsigned)((ttid + i * 128) * 16), src + ttid + i * 128);
}
__device__ __forceinline__ void teambar(int team) {
    asm volatile("bar.sync %0, 128;" :: "r"(team + 1) : "memory");
}

// ---------------------------------------------------------------------------
// Grid barrier
// ---------------------------------------------------------------------------
__device__ __forceinline__ void grid_sync(unsigned token) {
    __syncthreads();
    if (blockIdx.x == 0) {
        if (threadIdx.x > 0 && threadIdx.x < GBLK) {
            unsigned v;
            do {
                asm volatile("ld.acquire.gpu.global.u32 %0, [%1];"
                             : "=r"(v) : "l"(g_arrive + threadIdx.x * 32) : "memory");
            } while (v < token);
        }
        __syncthreads();
        if (threadIdx.x == 0) {
            asm volatile("st.release.gpu.global.u32 [%0], %1;"
                         :: "l"(&g_release), "r"(token) : "memory");
        }
    } else {
        if (threadIdx.x == 0) {
            asm volatile("st.release.gpu.global.u32 [%0], %1;"
                         :: "l"(g_arrive + blockIdx.x * 32), "r"(token) : "memory");
            unsigned v;
            do {
                asm volatile("ld.acquire.gpu.global.u32 %0, [%1];"
                             : "=r"(v) : "l"(&g_release) : "memory");
            } while (v < token);
        }
        __syncthreads();
    }
}

// ---------------------------------------------------------------------------
// One warp's quarter-chunk inner product: 6 GRU rows (2 jl) + optional
// posterior row. 2 batches per lane, 32 k (16 k-pair rows in team buffer).
// ---------------------------------------------------------------------------
template<bool POST>
__device__ __forceinline__ void gchunk2(const float* __restrict__ sb,
        const float* __restrict__ ar, const float* __restrict__ az,
        const float* __restrict__ an,
        const float* __restrict__ br, const float* __restrict__ bz,
        const float* __restrict__ bn,
        const float* __restrict__ wp,
        ull& rA0, ull& rA1, ull& zA0, ull& zA1, ull& nA0, ull& nA1,
        ull& rB0, ull& rB1, ull& zB0, ull& zB1, ull& nB0, ull& nB1,
        ull& P0, ull& P1)
{
#pragma unroll
    for (int i = 0; i < 8; ++i) {
        ulonglong2 a0 = *(const ulonglong2*)(sb + (2 * i) * 128);
        ulonglong2 a1 = *(const ulonglong2*)(sb + (2 * i + 1) * 128);
        ulonglong2 q;
        q = *(const ulonglong2*)(ar + 4 * i);
        ffma2(rA0, q.x, a0.x); ffma2(rA0, q.y, a1.x);
        ffma2(rA1, q.x, a0.y); ffma2(rA1, q.y, a1.y);
        q = *(const ulonglong2*)(az + 4 * i);
        ffma2(zA0, q.x, a0.x); ffma2(zA0, q.y, a1.x);
        ffma2(zA1, q.x, a0.y); ffma2(zA1, q.y, a1.y);
        q = *(const ulonglong2*)(an + 4 * i);
        ffma2(nA0, q.x, a0.x); ffma2(nA0, q.y, a1.x);
        ffma2(nA1, q.x, a0.y); ffma2(nA1, q.y, a1.y);
        q = *(const ulonglong2*)(br + 4 * i);
        ffma2(rB0, q.x, a0.x); ffma2(rB0, q.y, a1.x);
        ffma2(rB1, q.x, a0.y); ffma2(rB1, q.y, a1.y);
        q = *(const ulonglong2*)(bz + 4 * i);
        ffma2(zB0, q.x, a0.x); ffma2(zB0, q.y, a1.x);
        ffma2(zB1, q.x, a0.y); ffma2(zB1, q.y, a1.y);
        q = *(const ulonglong2*)(bn + 4 * i);
        ffma2(nB0, q.x, a0.x); ffma2(nB0, q.y, a1.x);
        ffma2(nB1, q.x, a0.y); ffma2(nB1, q.y, a1.y);
        if (POST) {
            q = *(const ulonglong2*)(wp + 4 * i);
            ffma2(P0, q.x, a0.x); ffma2(P0, q.y, a1.x);
            ffma2(P1, q.x, a0.y); ffma2(P1, q.y, a1.y);
        }
    }
}

__device__ __forceinline__ float gru_cell(float vr, float vz, float gi,
                                          float gh, float hp) {
    float r = 1.f / (1.f + __expf(-vr));
    float z = 1.f / (1.f + __expf(-vz));
    float n = tanhf(gi + r * gh);
    return (1.f - z) * n + z * hp;
}

__global__ void init_state_kernel() {
    const int idx = blockIdx.x * blockDim.x + threadIdx.x;
    const int stride = gridDim.x * blockDim.x;
    for (int i = idx; i < D_ * B_; i += stride) g_h[i] = 0.f;
    for (int i = idx; i < S_ * B_; i += stride) g_z[i] = 0.f;
    for (int i = idx; i < GBLK * 32; i += stride) g_arrive[i] = 0u;
    if (idx == 0) g_release = 0u;
}

__global__ void build_wx_kernel(const float* __restrict__ Wm,
                                const float* __restrict__ Wv,
                                const float* __restrict__ bm,
                                const float* __restrict__ bv) {
    const int n = blockIdx.x;
    const int s = n >> 1, mv = n & 1;
    const float* src = (mv ? Wv : Wm) + (size_t)s * (I_ + D_);
    float* dst = g_wx + (size_t)n * I_;
    for (int k = threadIdx.x; k < I_; k += blockDim.x) dst[k] = src[k];
    if (threadIdx.x == 0) g_bx[n] = mv ? bv[s] : bm[s];
}

// ---------------------------------------------------------------------------
// Persistent scan: 4 k-teams x 4 warps; per-team autonomous cp.async staging
// with named team barriers (no per-chunk block-wide syncs).
// ---------------------------------------------------------------------------
__global__ void __launch_bounds__(TPB, 1) scan_kernel(
    const float* __restrict__ W_ih, const float* __restrict__ W_hh,
    const float* __restrict__ b_ih, const float* __restrict__ b_hh,
    const float* __restrict__ Wm,   const float* __restrict__ Wv,
    const float* __restrict__ noise)
{
    extern __shared__ float sm[];
    float* s_whh  = sm;
    float* s_wih  = sm + OFF_WIH;
    float* s_wmvh = sm + OFF_WMVH;
    float* s_stg  = sm + OFF_STG;
    float* s_bih  = sm + OFF_B;
    float* s_bhh  = sm + OFF_B + 24;

    const unsigned stg_u = (unsigned)__cvta_generic_to_shared(s_stg);

    const int tid  = threadIdx.x;
    const int lane = tid & 31;
    const int wid  = tid >> 5;
    const int team = wid >> 2;        // 0..3 (k-quarter); threads contiguous
    const int ttid = tid & 127;       // thread id within team
    const int wj   = wid & 3;         // jl-pair 0..3; also posterior row
    const int bid  = blockIdx.x;
    const int j0g  = bid * JPB;
    const int s0g  = bid * SPB;
    const int jl0  = 2 * wj, jl1 = 2 * wj + 1;

    for (int v = tid; v < 24 * 256; v += TPB) {
        int row = v >> 8, c = v & 255;
        int jl = row / 3, g = row % 3;
        ((float4*)s_whh)[v] = ((const float4*)(W_hh + (size_t)(g * D_ + j0g + jl) * D_))[c];
    }
    for (int v = tid; v < 24 * 64; v += TPB) {
        int row = v >> 6, c = v & 63;
        int jl = row / 3, g = row % 3;
        ((float4*)s_wih)[v] = ((const float4*)(W_ih + (size_t)(g * D_ + j0g + jl) * S_))[c];
    }
    for (int v = tid; v < 4 * 256; v += TPB) {
        int row = v >> 8, c = v & 255;
        int sl = row >> 1, mv = row & 1;
        const float* W = (mv ? Wv : Wm) + (size_t)(s0g + sl) * (I_ + D_) + I_;
        ((float4*)s_wmvh)[v] = ((const float4*)W)[c];
    }
    if (tid < 24) {
        int jl = tid / 3, g = tid % 3;
        s_bih[tid] = b_ih[g * D_ + j0g + jl];
        s_bhh[tid] = b_hh[g * D_ + j0g + jl];
    }
    __syncthreads();

    // per-warp weight row base pointers
    const float* ihAr = s_wih + (jl0 * 3 + 0) * S_;
    const float* ihAz = s_wih + (jl0 * 3 + 1) * S_;
    const float* ihAn = s_wih + (jl0 * 3 + 2) * S_;
    const float* ihBr = s_wih + (jl1 * 3 + 0) * S_;
    const float* ihBz = s_wih + (jl1 * 3 + 1) * S_;
    const float* ihBn = s_wih + (jl1 * 3 + 2) * S_;
    const float* hhAr = s_whh + (jl0 * 3 + 0) * D_;
    const float* hhAz = s_whh + (jl0 * 3 + 1) * D_;
    const float* hhAn = s_whh + (jl0 * 3 + 2) * D_;
    const float* hhBr = s_whh + (jl1 * 3 + 0) * D_;
    const float* hhBz = s_whh + (jl1 * 3 + 1) * D_;
    const float* hhBn = s_whh + (jl1 * 3 + 2) * D_;
    const float* wpR  = s_wmvh + wj * D_;

    // per-team staging buffers (2048 floats each) and sources
    const unsigned tb0 = stg_u + (unsigned)team * 16384u;
    const unsigned tb1 = tb0 + 8192u;
    const float* sb0 = s_stg + team * 4096 + 4 * lane;
    const float* sb1 = sb0 + 2048;
    const float4* zsrc = (const float4*)g_z + team * 512;
    const float4* hsrc = (const float4*)g_h + team * 512;

    // carried accumulators (quarter partials)
    ull rA0 = 0, rA1 = 0, zA0 = 0, zA1 = 0, nA0 = 0, nA1 = 0;
    ull rB0 = 0, rB1 = 0, zB0 = 0, zB1 = 0, nB0 = 0, nB1 = 0;
    float hp0 = 0.f, hp1 = 0.f, hp2 = 0.f, hp3 = 0.f;
    ull du0, du1;

    cpa_team(tb0, zsrc, ttid); CP_COMMIT();      // z_{-1} quarter 0

    for (int t = 0; t < T_; ++t) {
        float2 px = make_float2(0.f, 0.f);
        float nz = 0.f;
        if (tid < 128) {
            int slq = tid >> 6, bq = tid & 63;
            px = __ldcg((const float2*)(g_postx +
                    ((size_t)bq * T_ + t) * (2 * S_) + 2 * (s0g + slq)));
            nz = __ldcg(noise + ((size_t)t * B_ + bq) * S_ + s0g + slq);
        }

        // ===== (A) gi over z_{t-1}: 2 team-quarter chunks =====
        ull gA0 = 0, gA1 = 0, gB0 = 0, gB1 = 0;   // gi n-gate
        {
            CP_WAIT0(); teambar(team);
            cpa_team(tb1, zsrc + 2048, ttid); CP_COMMIT();
            int off = team * 32;
            gchunk2<false>(sb0, ihAr + off, ihAz + off, ihAn + off,
                           ihBr + off, ihBz + off, ihBn + off, 0,
                           rA0, rA1, zA0, zA1, gA0, gA1,
                           rB0, rB1, zB0, zB1, gB0, gB1, du0, du1);
            CP_WAIT0(); teambar(team);
            off = 128 + team * 32;
            gchunk2<false>(sb1, ihAr + off, ihAz + off, ihAn + off,
                           ihBr + off, ihBz + off, ihBn + off, 0,
                           rA0, rA1, zA0, zA1, gA0, gA1,
                           rB0, rB1, zB0, zB1, gB0, gB1, du0, du1);
        }

        // ---- finalize h_t: 4-way cross-team reduce (floats, stride 17) ----
        {
            __syncthreads();    // all teams done reading staging buffers
            if (team != 0) {
                float* r = s_stg + ((team - 1) * 4 + wj) * 544 + lane * 17;
                r[0]  = sum2(rA0); r[1]  = sum2(rA1);
                r[2]  = sum2(zA0); r[3]  = sum2(zA1);
                r[4]  = sum2(gA0); r[5]  = sum2(gA1);
                r[6]  = sum2(nA0); r[7]  = sum2(nA1);
                r[8]  = sum2(rB0); r[9]  = sum2(rB1);
                r[10] = sum2(zB0); r[11] = sum2(zB1);
                r[12] = sum2(gB0); r[13] = sum2(gB1);
                r[14] = sum2(nB0); r[15] = sum2(nB1);
            }
            __syncthreads();
            if (team == 0) {
                float s[16];
                s[0]=sum2(rA0); s[1]=sum2(rA1); s[2]=sum2(zA0); s[3]=sum2(zA1);
                s[4]=sum2(gA0); s[5]=sum2(gA1); s[6]=sum2(nA0); s[7]=sum2(nA1);
                s[8]=sum2(rB0); s[9]=sum2(rB1); s[10]=sum2(zB0); s[11]=sum2(zB1);
                s[12]=sum2(gB0); s[13]=sum2(gB1); s[14]=sum2(nB0); s[15]=sum2(nB1);
#pragma unroll
                for (int tm = 0; tm < 3; ++tm) {
                    const float* r = s_stg + (tm * 4 + wj) * 544 + lane * 17;
#pragma unroll
                    for (int q = 0; q < 16; ++q) s[q] += r[q];
                }
                float brA = s_bih[jl0*3+0] + s_bhh[jl0*3+0];
                float bzA = s_bih[jl0*3+1] + s_bhh[jl0*3+1];
                float biA = s_bih[jl0*3+2], bhA = s_bhh[jl0*3+2];
                float brB = s_bih[jl1*3+0] + s_bhh[jl1*3+0];
                float bzB = s_bih[jl1*3+1] + s_bhh[jl1*3+1];
                float biB = s_bih[jl1*3+2], bhB = s_bhh[jl1*3+2];

                float hnA0 = gru_cell(s[0]+brA, s[2]+bzA, s[4]+biA, s[6]+bhA, hp0);
                float hnA1 = gru_cell(s[1]+brA, s[3]+bzA, s[5]+biA, s[7]+bhA, hp1);
                float hnB0 = gru_cell(s[8]+brB, s[10]+bzB, s[12]+biB, s[14]+bhB, hp2);
                float hnB1 = gru_cell(s[9]+brB, s[11]+bzB, s[13]+biB, s[15]+bhB, hp3);
                hp0 = hnA0; hp1 = hnA1; hp2 = hnB0; hp3 = hnB1;

                int jp = (j0g >> 1) + wj;
                float4 hv = make_float4(hnA0, hnB0, hnA1, hnB1);
                __stcg((float4*)g_h + jp * 32 + lane, hv);
                __stcg((float2*)(g_rssm + ((size_t)(2*lane) * T_ + t) * R_ + j0g + jl0),
                       make_float2(hnA0, hnB0));
                __stcg((float2*)(g_rssm + ((size_t)(2*lane+1) * T_ + t) * R_ + j0g + jl0),
                       make_float2(hnA1, hnB1));
            }
            rA0 = 0; rA1 = 0; zA0 = 0; zA1 = 0; nA0 = 0; nA1 = 0;
            rB0 = 0; rB1 = 0; zB0 = 0; zB1 = 0; nB0 = 0; nB1 = 0;
        }

        grid_sync(2 * t + 1);
        cpa_team(tb0, hsrc, ttid); CP_COMMIT();      // h chunk 0 quarter

        // ===== (B) h-pass over h_t: 8 team-quarter chunks, team-local sync ====
        ull P0 = 0, P1 = 0;
        for (int c = 0; c < 8; ++c) {
            CP_WAIT0(); teambar(team);               // chunk c landed, c-1 reads done
            if (c < 7) {
                cpa_team((c & 1) ? tb0 : tb1, hsrc + (c + 1) * 2048, ttid);
                CP_COMMIT();
            }
            const float* buf = (c & 1) ? sb1 : sb0;
            int off = c * 128 + team * 32;
            gchunk2<true>(buf, hhAr + off, hhAz + off, hhAn + off,
                          hhBr + off, hhBz + off, hhBn + off, wpR + off,
                          rA0, rA1, zA0, zA1, nA0, nA1,
                          rB0, rB1, zB0, zB1, nB0, nB1, P0, P1);
        }

        // ---- finalize z_t: 16-piece posterior reduce ----
        {
            __syncthreads();    // all teams done with staging buffers
            ull* red2 = (ull*)s_stg;
            *(ulonglong2*)(red2 + (size_t)(team * 4 + wj) * 64 + 2 * lane) =
                make_ulonglong2(P0, P1);
            __syncthreads();
            if (tid < 128) {
                int sl = tid >> 6, b = tid & 63;
                float m = px.x, v = px.y;
#pragma unroll
                for (int tm = 0; tm < 4; ++tm) {
                    m += sum2(red2[(size_t)(tm * 4 + 2 * sl) * 64 + b]);
                    v += sum2(red2[(size_t)(tm * 4 + 2 * sl + 1) * 64 + b]);
                }
                float zv = nz * __expf(0.5f * v) + m;
                int sg = s0g + sl;
                __stcg(&g_z[(size_t)(sg >> 1) * 128 + b * 2 + (sg & 1)], zv);
                g_rssm[((size_t)b * T_ + t) * R_ + D_ + sg] = zv;
            }
        }

        grid_sync(2 * t + 2);
        cpa_team(tb0, zsrc, ttid); CP_COMMIT();      // next step's z quarter 0
    }
}

// ---------------------------------------------------------------------------
// Decoder GEMM, packed-f32x2, GK=32, double-buffered smem (unchanged).
// ---------------------------------------------------------------------------
#define GM 128
#define GN 64
#define GK 32
#define KK2 (GK / 2)

__global__ void __launch_bounds__(256, 2) gemm_f32x2_kernel(
    const float* __restrict__ A, const float* __restrict__ W,
    const float* __restrict__ bias, float* __restrict__ C,
    int M, int N, int K, int act)
{
    __shared__ ull As2[2][KK2][GM];
    __shared__ ull Ws2[2][KK2][GN];
    const int tid = threadIdx.x;
    const int bm = blockIdx.y * GM;
    const int bn = blockIdx.x * GN;
    const int tx = tid & 15, ty = tid >> 4;
    const int m0 = ty * 8, n0 = tx * 4;
    const int part = tid & 7;
    const int lrow = tid >> 3;

    ull acc[8][4];
#pragma unroll
    for (int i = 0; i < 8; ++i)
#pragma unroll
        for (int j = 0; j < 4; ++j) acc[i][j] = 0ULL;

    float4 va[4], vw[2];
#pragma unroll
    for (int i = 0; i < 4; ++i)
        va[i] = *(const float4*)(A + (size_t)(bm + lrow + i * 32) * K + part * 4);
#pragma unroll
    for (int i = 0; i < 2; ++i)
        vw[i] = *(const float4*)(W + (size_t)(bn + lrow + i * 32) * K + part * 4);

#pragma unroll
    for (int i = 0; i < 4; ++i) {
        As2[0][part * 2 + 0][lrow + i * 32] = packf2(va[i].x, va[i].y);
        As2[0][part * 2 + 1][lrow + i * 32] = packf2(va[i].z, va[i].w);
    }
#pragma unroll
    for (int i = 0; i < 2; ++i) {
        Ws2[0][part * 2 + 0][lrow + i * 32] = packf2(vw[i].x, vw[i].y);
        Ws2[0][part * 2 + 1][lrow + i * 32] = packf2(vw[i].z, vw[i].w);
    }

    const int niter = K / GK;
    int buf = 0;
    for (int kb = 0; kb < niter; ++kb) {
        __syncthreads();
        if (kb + 1 < niter) {
            int ko = (kb + 1) * GK + part * 4;
#pragma unroll
            for (int i = 0; i < 4; ++i)
                va[i] = *(const float4*)(A + (size_t)(bm + lrow + i * 32) * K + ko);
#pragma unroll
            for (int i = 0; i < 2; ++i)
                vw[i] = *(const float4*)(W + (size_t)(bn + lrow + i * 32) * K + ko);
        }
#pragma unroll
        for (int k2 = 0; k2 < KK2; ++k2) {
            ull ra[8], rw[4];
            *(ulonglong2*)&ra[0] = *(const ulonglong2*)&As2[buf][k2][m0 + 0];
            *(ulonglong2*)&ra[2] = *(const ulonglong2*)&As2[buf][k2][m0 + 2];
            *(ulonglong2*)&ra[4] = *(const ulonglong2*)&As2[buf][k2][m0 + 4];
            *(ulonglong2*)&ra[6] = *(const ulonglong2*)&As2[buf][k2][m0 + 6];
            *(ulonglong2*)&rw[0] = *(const ulonglong2*)&Ws2[buf][k2][n0 + 0];
            *(ulonglong2*)&rw[2] = *(const ulonglong2*)&Ws2[buf][k2][n0 + 2];
#pragma unroll
            for (int i = 0; i < 8; ++i)
#pragma unroll
                for (int j = 0; j < 4; ++j) ffma2(acc[i][j], ra[i], rw[j]);
        }
        if (kb + 1 < niter) {
            int nb = buf ^ 1;
#pragma unroll
            for (int i = 0; i < 4; ++i) {
                As2[nb][part * 2 + 0][lrow + i * 32] = packf2(va[i].x, va[i].y);
                As2[nb][part * 2 + 1][lrow + i * 32] = packf2(va[i].z, va[i].w);
            }
#pragma unroll
            for (int i = 0; i < 2; ++i) {
                Ws2[nb][part * 2 + 0][lrow + i * 32] = packf2(vw[i].x, vw[i].y);
                Ws2[nb][part * 2 + 1][lrow + i * 32] = packf2(vw[i].z, vw[i].w);
            }
            buf = nb;
        }
    }

    float bb[4];
#pragma unroll
    for (int j = 0; j < 4; ++j) bb[j] = bias[bn + n0 + j];
#pragma unroll
    for (int i = 0; i < 8; ++i) {
        float r[4];
#pragma unroll
        for (int j = 0; j < 4; ++j) {
            float v = sum2(acc[i][j]) + bb[j];
            r[j] = act ? (v > 0.f ? v : expm1f(v)) : v;
        }
        *(float4*)(C + (size_t)(bm + m0 + i) * N + bn + n0) =
            make_float4(r[0], r[1], r[2], r[3]);
    }
}

// ---------------------------------------------------------------------------
// Epilogue
// ---------------------------------------------------------------------------
__global__ void epilogue_kernel(const float* __restrict__ x, float* __restrict__ out) {
    size_t idx = (size_t)blockIdx.x * blockDim.x + threadIdx.x;
    const size_t total = (size_t)B_ * T_ * I_;
    if (idx >= total) return;
    int i = (int)(idx & (I_ - 1));
    size_t bt = idx >> 9;
    int t = (int)(bt & (T_ - 1));
    int b = (int)(bt >> 8);

    float xh;
    if (t == 0) xh = x[idx];
    else        xh = x[idx - I_] + g_dist[idx - I_];
    out[(size_t)B_ * (T_ - 1) * I_ + idx] = xh;

    if (t < T_ - 1)
        out[((size_t)b * (T_ - 1) + t) * I_ + i] = g_dist[idx];
}

// ---------------------------------------------------------------------------
// kernel_launch
// ---------------------------------------------------------------------------
extern "C" void kernel_launch(void* const* d_in, const int* in_sizes, int n_in,
                              void* d_out, int out_size) {
    const float* x     = (const float*)d_in[0];
    const float* noise = (const float*)d_in[1];
    const float* W_ih  = (const float*)d_in[2];
    const float* W_hh  = (const float*)d_in[3];
    const float* b_ih  = (const float*)d_in[4];
    const float* b_hh  = (const float*)d_in[5];
    const float* Wm    = (const float*)d_in[6];
    const float* bm    = (const float*)d_in[7];
    const float* Wv    = (const float*)d_in[8];
    const float* bv    = (const float*)d_in[9];
    const float* dW0   = (const float*)d_in[10];
    const float* db0   = (const float*)d_in[11];
    const float* dW1   = (const float*)d_in[12];
    const float* db1   = (const float*)d_in[13];
    const float* dW2   = (const float*)d_in[14];
    const float* db2   = (const float*)d_in[15];
    const float* dW3   = (const float*)d_in[16];
    const float* db3   = (const float*)d_in[17];
    float* out = (float*)d_out;

    cudaFuncSetAttribute(scan_kernel, cudaFuncAttributeMaxDynamicSharedMemorySize,
                         SCAN_SMEM_BYTES);

    void *p_rssm, *p_a0, *p_a1, *p_dist, *p_wx, *p_bx, *p_postx;
    cudaGetSymbolAddress(&p_rssm, g_rssm);
    cudaGetSymbolAddress(&p_a0, g_a0);
    cudaGetSymbolAddress(&p_a1, g_a1);
    cudaGetSymbolAddress(&p_dist, g_dist);
    cudaGetSymbolAddress(&p_wx, g_wx);
    cudaGetSymbolAddress(&p_bx, g_bx);
    cudaGetSymbolAddress(&p_postx, g_postx);

    const int M = B_ * T_;  // 16384

    init_state_kernel<<<64, 256>>>();
    build_wx_kernel<<<2 * S_, 256>>>(Wm, Wv, bm, bv);

    gemm_f32x2_kernel<<<dim3((2 * S_) / GN, M / GM), 256>>>(
        x, (const float*)p_wx, (const float*)p_bx, (float*)p_postx,
        M, 2 * S_, I_, 0);

    scan_kernel<<<GBLK, TPB, SCAN_SMEM_BYTES>>>(W_ih, W_hh, b_ih, b_hh,
                                                Wm, Wv, noise);

    gemm_f32x2_kernel<<<dim3(H_ / GN, M / GM), 256>>>(
        (const float*)p_rssm, dW0, db0, (float*)p_a0, M, H_, R_, 1);
    gemm_f32x2_kernel<<<dim3(H_ / GN, M / GM), 256>>>(
        (const float*)p_a0, dW1, db1, (float*)p_a1, M, H_, H_, 1);
    gemm_f32x2_kernel<<<dim3(H_ / GN, M / GM), 256>>>(
        (const float*)p_a1, dW2, db2, (float*)p_a0, M, H_, H_, 1);
    gemm_f32x2_kernel<<<dim3(I_ / GN, M / GM), 256>>>(
        (const float*)p_a0, dW3, db3, (float*)p_dist, M, I_, H_, 0);

    epilogue_kernel<<<(B_ * T_ * I_ + 255) / 256, 256>>>(x, out);
}